// round 4
// baseline (speedup 1.0000x reference)
#include <cuda_runtime.h>
#include <cuda_bf16.h>
#include <math.h>

// ---------------------------------------------------------------------------
// CriticRNN: T=128, B=128, OBS=512, H=1024
// ---------------------------------------------------------------------------

#define TT  128
#define BB  128
#define OBS 512
#define HH  1024
#define H3  3072
#define MM  (TT * BB)   // 16384

typedef unsigned long long u64;

// Static device scratch (no allocations allowed)
__device__ float g_emb[(size_t)MM * HH];      // 64 MB
__device__ float g_xi[(size_t)MM * H3];       // 192 MB
__device__ float g_y[(size_t)MM * HH];        // 64 MB
__device__ float g_critic[(size_t)MM * HH];   // 64 MB
__device__ float g_WhT[(size_t)H3 * HH];      // 12 MB  (Wh transposed: [3H][H])
__device__ float g_mask[MM];                  // keep-mask: 1.0 = keep, 0.0 = reset
__device__ int   g_bytemode;
__device__ unsigned g_bar;                    // grid barrier counter

// ---------------------------------------------------------------------------
// dones layout detection + mask expansion (byte-bool vs int32).
// ---------------------------------------------------------------------------
__global__ void detect_mask_mode(const unsigned int* __restrict__ d)
{
    __shared__ int flag;
    if (threadIdx.x == 0) flag = 0;
    __syncthreads();
    int f = 0;
    for (int i = threadIdx.x; i < MM / 4; i += blockDim.x)
        if (d[i] > 1u) f = 1;
    if (f) atomicOr(&flag, 1);
    __syncthreads();
    if (threadIdx.x == 0) g_bytemode = flag;
}

__global__ void expand_mask(const void* __restrict__ dones, float* __restrict__ mask)
{
    const int i = blockIdx.x * blockDim.x + threadIdx.x;
    if (i >= MM) return;
    int done;
    if (g_bytemode)
        done = ((const unsigned char*)dones)[i] != 0;
    else
        done = ((const int*)dones)[i] != 0;
    mask[i] = done ? 0.f : 1.f;
}

// ---------------------------------------------------------------------------
// Wh [H][3H] -> WhT [3H][H]
// ---------------------------------------------------------------------------
__global__ void transpose_wh(const float* __restrict__ Wh, float* __restrict__ WhT)
{
    __shared__ float tile[32][33];
    const int x = blockIdx.x * 32 + threadIdx.x;   // col in Wh (3H)
    const int y = blockIdx.y * 32 + threadIdx.y;   // k (H)
    #pragma unroll
    for (int i = 0; i < 32; i += 8)
        tile[threadIdx.y + i][threadIdx.x] = Wh[(size_t)(y + i) * H3 + x];
    __syncthreads();
    const int x2 = blockIdx.y * 32 + threadIdx.x;  // k
    const int y2 = blockIdx.x * 32 + threadIdx.y;  // col
    #pragma unroll
    for (int i = 0; i < 32; i += 8)
        WhT[(size_t)(y2 + i) * HH + x2] = tile[threadIdx.x][threadIdx.y + i];
}

// ---------------------------------------------------------------------------
// fp32 SGEMM, double-buffered smem: C[M,N] = op(A[M,K] @ B[K,N] + bias[N])
// BM=BN=128, BK=8, 256 threads, 8x8 per thread.
// ---------------------------------------------------------------------------
template <int DO_RELU>
__global__ __launch_bounds__(256, 2)
void sgemm128(const float* __restrict__ A, const float* __restrict__ B,
              const float* __restrict__ bias, float* __restrict__ C,
              int M, int N, int K)
{
    __shared__ float As[2][8][128];
    __shared__ float Bs[2][8][128];

    const int tid  = threadIdx.x;
    const int cRow = blockIdx.y * 128;
    const int cCol = blockIdx.x * 128;

    const int rowA = tid >> 1;
    const int colA = (tid & 1) << 2;
    const int rowB = tid >> 5;
    const int colB = (tid & 31) << 2;

    const int tx = tid & 15;
    const int ty = tid >> 4;

    float acc[8][8];
    #pragma unroll
    for (int i = 0; i < 8; i++)
        #pragma unroll
        for (int j = 0; j < 8; j++) acc[i][j] = 0.f;

    const float* Ap = A + (size_t)(cRow + rowA) * K + colA;
    const float* Bp = B + cCol + colB + (size_t)rowB * N;

    float4 a4 = *(const float4*)(Ap);
    float4 b4 = *(const float4*)(Bp);
    As[0][colA + 0][rowA] = a4.x;
    As[0][colA + 1][rowA] = a4.y;
    As[0][colA + 2][rowA] = a4.z;
    As[0][colA + 3][rowA] = a4.w;
    *(float4*)&Bs[0][rowB][colB] = b4;
    __syncthreads();

    int buf = 0;
    for (int kb = 0; kb < K; kb += 8) {
        const bool more = (kb + 8) < K;
        if (more) {
            a4 = *(const float4*)(Ap + kb + 8);
            b4 = *(const float4*)(Bp + (size_t)(kb + 8) * N);
        }

        #pragma unroll
        for (int k = 0; k < 8; k++) {
            float regM[8], regN[8];
            *(float4*)&regM[0] = *(const float4*)&As[buf][k][ty * 8];
            *(float4*)&regM[4] = *(const float4*)&As[buf][k][ty * 8 + 4];
            *(float4*)&regN[0] = *(const float4*)&Bs[buf][k][tx * 8];
            *(float4*)&regN[4] = *(const float4*)&Bs[buf][k][tx * 8 + 4];
            #pragma unroll
            for (int i = 0; i < 8; i++)
                #pragma unroll
                for (int j = 0; j < 8; j++)
                    acc[i][j] += regM[i] * regN[j];
        }

        if (more) {
            const int nb = buf ^ 1;
            As[nb][colA + 0][rowA] = a4.x;
            As[nb][colA + 1][rowA] = a4.y;
            As[nb][colA + 2][rowA] = a4.z;
            As[nb][colA + 3][rowA] = a4.w;
            *(float4*)&Bs[nb][rowB][colB] = b4;
        }
        buf ^= 1;
        __syncthreads();
    }

    #pragma unroll
    for (int i = 0; i < 8; i++) {
        const int r = cRow + ty * 8 + i;
        #pragma unroll
        for (int j = 0; j < 8; j += 4) {
            const int c = cCol + tx * 8 + j;
            float4 v;
            v.x = acc[i][j + 0] + bias[c + 0];
            v.y = acc[i][j + 1] + bias[c + 1];
            v.z = acc[i][j + 2] + bias[c + 2];
            v.w = acc[i][j + 3] + bias[c + 3];
            if (DO_RELU) {
                v.x = fmaxf(v.x, 0.f); v.y = fmaxf(v.y, 0.f);
                v.z = fmaxf(v.z, 0.f); v.w = fmaxf(v.w, 0.f);
            }
            *(float4*)&C[(size_t)r * N + c] = v;
        }
    }
}

// ---------------------------------------------------------------------------
// Packed f32x2 FMA helpers
// ---------------------------------------------------------------------------
__device__ __forceinline__ u64 ffma2(u64 a, u64 b, u64 c)
{
    u64 d;
    asm("fma.rn.f32x2 %0, %1, %2, %3;" : "=l"(d) : "l"(a), "l"(b), "l"(c));
    return d;
}
union F4U { float4 v; u64 d[2]; };
union U64F { u64 d; float2 f; };

// ---------------------------------------------------------------------------
// Persistent GRU scan: one kernel runs all 128 steps with a software grid
// barrier between steps. 128 blocks (grid 32x4, tile 32 batch x 32 hcols x
// 3 gates), 192 threads, thread = 4 rows x 4 cols x 1 gate, k packed in
// f32x2 pairs. Weights read from WhT [3H][H] (k-contiguous per column).
// ---------------------------------------------------------------------------
struct SmemP {
    float hs[2][32][40];   // [buf][row][k]    stride 160B
    float ws[2][96][36];   // [buf][gcol][k]   stride 144B
};
struct SmemE {
    float es[3][32][32];   // gate partials
};

__global__ __launch_bounds__(192, 1)
void gru_scan(const float* __restrict__ hidden,
              const float* __restrict__ mask,     // [T*B] keep-mask
              const float* __restrict__ xi,       // [T,B,3H]
              const float* __restrict__ WhT,      // [3H][H]
              const float* __restrict__ bhn,      // [H]
              float* __restrict__ y)              // [T,B,H]
{
    __shared__ __align__(16) unsigned char smraw[sizeof(SmemP)];
    SmemP* sp = (SmemP*)smraw;
    SmemE* se = (SmemE*)smraw;

    const int tid = threadIdx.x;
    const int bn  = blockIdx.x * 32;   // h-column base
    const int bm  = blockIdx.y * 32;   // batch-row base

    // compute mapping
    const int g   = tid / 64;          // gate 0..2
    const int t2  = tid % 64;
    const int r0  = (t2 >> 3) << 2;    // rows r0..r0+3
    const int c0  = (t2 & 7) << 2;     // cols c0..c0+3
    const int wc0 = g * 32 + c0;

    // h loader mapping: f = tid covers rows 0..23; f2 = tid+192 rows 24..31 (tid<64)
    const int hlr  = tid >> 3;
    const int hlk  = (tid & 7) << 2;
    const int hlr2 = 24 + (tid >> 3);
    const bool h2v = (tid < 64);

    // w loader: 4 float4 per thread
    const float* wp[4];
    int wcol[4], wkq[4];
    #pragma unroll
    for (int i = 0; i < 4; i++) {
        const int f = tid + 192 * i;
        const int c = f >> 3;
        const int kq = (f & 7) << 2;
        wcol[i] = c;
        wkq[i]  = kq;
        wp[i]   = WhT + (size_t)((c >> 5) * HH + bn + (c & 31)) * HH + kq;
    }

    for (int t = 0; t < TT; t++) {
        const float* prev = (t == 0) ? hidden : (y + (size_t)(t - 1) * BB * HH);
        const float* mt   = mask + (size_t)t * BB;
        const float* xi_t = xi + (size_t)t * BB * H3;
        float* out        = y + (size_t)t * BB * HH;

        const float dm0 = mt[bm + hlr];
        const float dm1 = h2v ? mt[bm + hlr2] : 0.f;

        const float* hbase  = prev + (size_t)(bm + hlr) * HH + hlk;
        const float* hbase2 = h2v ? (prev + (size_t)(bm + hlr2) * HH + hlk) : hbase;

        // prologue: load tile kb=0
        float4 ph0 = *(const float4*)(hbase);
        float4 ph1 = *(const float4*)(hbase2);
        float4 pw0 = *(const float4*)(wp[0]);
        float4 pw1 = *(const float4*)(wp[1]);
        float4 pw2 = *(const float4*)(wp[2]);
        float4 pw3 = *(const float4*)(wp[3]);
        {
            float4 m0 = make_float4(ph0.x * dm0, ph0.y * dm0, ph0.z * dm0, ph0.w * dm0);
            *(float4*)&sp->hs[0][hlr][hlk] = m0;
            if (h2v) {
                float4 m1 = make_float4(ph1.x * dm1, ph1.y * dm1, ph1.z * dm1, ph1.w * dm1);
                *(float4*)&sp->hs[0][hlr2][hlk] = m1;
            }
            *(float4*)&sp->ws[0][wcol[0]][wkq[0]] = pw0;
            *(float4*)&sp->ws[0][wcol[1]][wkq[1]] = pw1;
            *(float4*)&sp->ws[0][wcol[2]][wkq[2]] = pw2;
            *(float4*)&sp->ws[0][wcol[3]][wkq[3]] = pw3;
        }
        __syncthreads();

        u64 acc2[4][4];
        #pragma unroll
        for (int i = 0; i < 4; i++)
            #pragma unroll
            for (int j = 0; j < 4; j++) acc2[i][j] = 0ull;

        int buf = 0;
        #pragma unroll 1
        for (int kb = 0; kb < HH; kb += 32) {
            const bool more = (kb + 32) < HH;
            if (more) {
                ph0 = *(const float4*)(hbase + kb + 32);
                if (h2v) ph1 = *(const float4*)(hbase2 + kb + 32);
                pw0 = *(const float4*)(wp[0] + kb + 32);
                pw1 = *(const float4*)(wp[1] + kb + 32);
                pw2 = *(const float4*)(wp[2] + kb + 32);
                pw3 = *(const float4*)(wp[3] + kb + 32);
            }

            #pragma unroll
            for (int k4 = 0; k4 < 32; k4 += 4) {
                F4U h0, h1, h2, h3, w0, w1, w2, w3;
                h0.v = *(const float4*)&sp->hs[buf][r0 + 0][k4];
                h1.v = *(const float4*)&sp->hs[buf][r0 + 1][k4];
                h2.v = *(const float4*)&sp->hs[buf][r0 + 2][k4];
                h3.v = *(const float4*)&sp->hs[buf][r0 + 3][k4];
                w0.v = *(const float4*)&sp->ws[buf][wc0 + 0][k4];
                w1.v = *(const float4*)&sp->ws[buf][wc0 + 1][k4];
                w2.v = *(const float4*)&sp->ws[buf][wc0 + 2][k4];
                w3.v = *(const float4*)&sp->ws[buf][wc0 + 3][k4];
                #pragma unroll
                for (int p = 0; p < 2; p++) {
                    acc2[0][0] = ffma2(h0.d[p], w0.d[p], acc2[0][0]);
                    acc2[0][1] = ffma2(h0.d[p], w1.d[p], acc2[0][1]);
                    acc2[0][2] = ffma2(h0.d[p], w2.d[p], acc2[0][2]);
                    acc2[0][3] = ffma2(h0.d[p], w3.d[p], acc2[0][3]);
                    acc2[1][0] = ffma2(h1.d[p], w0.d[p], acc2[1][0]);
                    acc2[1][1] = ffma2(h1.d[p], w1.d[p], acc2[1][1]);
                    acc2[1][2] = ffma2(h1.d[p], w2.d[p], acc2[1][2]);
                    acc2[1][3] = ffma2(h1.d[p], w3.d[p], acc2[1][3]);
                    acc2[2][0] = ffma2(h2.d[p], w0.d[p], acc2[2][0]);
                    acc2[2][1] = ffma2(h2.d[p], w1.d[p], acc2[2][1]);
                    acc2[2][2] = ffma2(h2.d[p], w2.d[p], acc2[2][2]);
                    acc2[2][3] = ffma2(h2.d[p], w3.d[p], acc2[2][3]);
                    acc2[3][0] = ffma2(h3.d[p], w0.d[p], acc2[3][0]);
                    acc2[3][1] = ffma2(h3.d[p], w1.d[p], acc2[3][1]);
                    acc2[3][2] = ffma2(h3.d[p], w2.d[p], acc2[3][2]);
                    acc2[3][3] = ffma2(h3.d[p], w3.d[p], acc2[3][3]);
                }
            }

            if (more) {
                const int nb = buf ^ 1;
                float4 m0 = make_float4(ph0.x * dm0, ph0.y * dm0, ph0.z * dm0, ph0.w * dm0);
                *(float4*)&sp->hs[nb][hlr][hlk] = m0;
                if (h2v) {
                    float4 m1 = make_float4(ph1.x * dm1, ph1.y * dm1, ph1.z * dm1, ph1.w * dm1);
                    *(float4*)&sp->hs[nb][hlr2][hlk] = m1;
                }
                *(float4*)&sp->ws[nb][wcol[0]][wkq[0]] = pw0;
                *(float4*)&sp->ws[nb][wcol[1]][wkq[1]] = pw1;
                *(float4*)&sp->ws[nb][wcol[2]][wkq[2]] = pw2;
                *(float4*)&sp->ws[nb][wcol[3]][wkq[3]] = pw3;
            }
            __syncthreads();
            buf ^= 1;
        }

        // reduce f32x2 pairs and stash gate partials (overlays ws/hs region;
        // safe: final __syncthreads above ended all tile reads)
        #pragma unroll
        for (int i = 0; i < 4; i++) {
            float4 o;
            U64F u;
            u.d = acc2[i][0]; o.x = u.f.x + u.f.y;
            u.d = acc2[i][1]; o.y = u.f.x + u.f.y;
            u.d = acc2[i][2]; o.z = u.f.x + u.f.y;
            u.d = acc2[i][3]; o.w = u.f.x + u.f.y;
            *(float4*)&se->es[g][r0 + i][c0] = o;
        }
        __syncthreads();

        // epilogue: 256 float4 outputs, thread handles f=tid (+ f2=tid+192)
        #pragma unroll
        for (int pass = 0; pass < 2; pass++) {
            if (pass == 1 && !h2v) break;
            const int lr = (pass == 0) ? hlr : hlr2;
            const float mk = (pass == 0) ? dm0 : dm1;
            const int b = bm + lr;
            const int j = bn + hlk;

            float4 aR = *(const float4*)&se->es[0][lr][hlk];
            float4 aZ = *(const float4*)&se->es[1][lr][hlk];
            float4 aN = *(const float4*)&se->es[2][lr][hlk];
            float4 hp = *(const float4*)(prev + (size_t)b * HH + j);
            float4 xr = *(const float4*)(xi_t + (size_t)b * H3 + j);
            float4 xz = *(const float4*)(xi_t + (size_t)b * H3 + HH + j);
            float4 xn = *(const float4*)(xi_t + (size_t)b * H3 + 2 * HH + j);
            float4 bh = *(const float4*)(bhn + j);

            float4 o;
            {
                const float r = 1.f / (1.f + expf(-(xr.x + aR.x)));
                const float z = 1.f / (1.f + expf(-(xz.x + aZ.x)));
                const float n = tanhf(xn.x + r * (aN.x + bh.x));
                o.x = (1.f - z) * n + z * (hp.x * mk);
            }
            {
                const float r = 1.f / (1.f + expf(-(xr.y + aR.y)));
                const float z = 1.f / (1.f + expf(-(xz.y + aZ.y)));
                const float n = tanhf(xn.y + r * (aN.y + bh.y));
                o.y = (1.f - z) * n + z * (hp.y * mk);
            }
            {
                const float r = 1.f / (1.f + expf(-(xr.z + aR.z)));
                const float z = 1.f / (1.f + expf(-(xz.z + aZ.z)));
                const float n = tanhf(xn.z + r * (aN.z + bh.z));
                o.z = (1.f - z) * n + z * (hp.z * mk);
            }
            {
                const float r = 1.f / (1.f + expf(-(xr.w + aR.w)));
                const float z = 1.f / (1.f + expf(-(xz.w + aZ.w)));
                const float n = tanhf(xn.w + r * (aN.w + bh.w));
                o.w = (1.f - z) * n + z * (hp.w * mk);
            }
            *(float4*)(out + (size_t)b * HH + j) = o;
        }

        // grid barrier (skip after last step)
        if (t < TT - 1) {
            __syncthreads();
            if (tid == 0) {
                __threadfence();
                atomicAdd(&g_bar, 1u);
                const unsigned target = (unsigned)(gridDim.x * gridDim.y) * (t + 1);
                while (*((volatile unsigned*)&g_bar) < target) { }
                __threadfence();
            }
            __syncthreads();
        }
    }
}

// ---------------------------------------------------------------------------
// value[m] = sum_j critic[m,j] * W2[j] + b2 ; one block per row m
// ---------------------------------------------------------------------------
__global__ __launch_bounds__(256)
void value_kernel(const float* __restrict__ critic, const float* __restrict__ W2,
                  const float* __restrict__ b2, float* __restrict__ out)
{
    const int m   = blockIdx.x;
    const int tid = threadIdx.x;
    float s = 0.f;
    const float* row = critic + (size_t)m * HH;
    for (int j = tid * 4; j < HH; j += 256 * 4) {
        float4 c4 = *(const float4*)(row + j);
        float4 w4 = *(const float4*)(W2 + j);
        s += c4.x * w4.x + c4.y * w4.y + c4.z * w4.z + c4.w * w4.w;
    }
    #pragma unroll
    for (int off = 16; off > 0; off >>= 1)
        s += __shfl_down_sync(0xffffffffu, s, off);
    __shared__ float red[8];
    if ((tid & 31) == 0) red[tid >> 5] = s;
    __syncthreads();
    if (tid == 0) {
        float t = 0.f;
        #pragma unroll
        for (int w = 0; w < 8; w++) t += red[w];
        out[m] = t + b2[0];
    }
}

__global__ void copy_hout(const float* __restrict__ src, float* __restrict__ dst)
{
    const int i = (blockIdx.x * blockDim.x + threadIdx.x) * 4;
    *(float4*)&dst[i] = *(const float4*)&src[i];
}

// ---------------------------------------------------------------------------
// Launch
// ---------------------------------------------------------------------------
extern "C" void kernel_launch(void* const* d_in, const int* in_sizes, int n_in,
                              void* d_out, int out_size)
{
    const float* hidden = (const float*)d_in[0];
    const float* ws     = (const float*)d_in[1];          // [T,B,OBS]
    const void*  dones  = (const void*)d_in[2];           // [T,B] bool/int32
    const float* W_emb  = (const float*)d_in[3];
    const float* b_emb  = (const float*)d_in[4];
    const float* Wi     = (const float*)d_in[5];
    const float* bi     = (const float*)d_in[6];
    const float* Wh     = (const float*)d_in[7];
    const float* bhn    = (const float*)d_in[8];
    const float* W1     = (const float*)d_in[9];
    const float* b1     = (const float*)d_in[10];
    const float* W2     = (const float*)d_in[11];
    const float* b2     = (const float*)d_in[12];
    float* out = (float*)d_out;

    float *emb, *xi, *y, *critic, *mask, *whT;
    unsigned* barp;
    cudaGetSymbolAddress((void**)&emb,    g_emb);
    cudaGetSymbolAddress((void**)&xi,     g_xi);
    cudaGetSymbolAddress((void**)&y,      g_y);
    cudaGetSymbolAddress((void**)&critic, g_critic);
    cudaGetSymbolAddress((void**)&mask,   g_mask);
    cudaGetSymbolAddress((void**)&whT,    g_WhT);
    cudaGetSymbolAddress((void**)&barp,   g_bar);

    // 0) reset grid barrier; mask detection/expansion; weight transpose
    cudaMemsetAsync(barp, 0, sizeof(unsigned));
    detect_mask_mode<<<1, 256>>>((const unsigned int*)dones);
    expand_mask<<<MM / 256, 256>>>(dones, mask);
    {
        dim3 grid(H3 / 32, HH / 32), blk(32, 8);
        transpose_wh<<<grid, blk>>>(Wh, whT);
    }

    // 1) emb = relu(WS @ W_emb + b_emb)   [16384, 1024]
    {
        dim3 grid(HH / 128, MM / 128);
        sgemm128<1><<<grid, 256>>>(ws, W_emb, b_emb, emb, MM, HH, OBS);
    }
    // 2) xi = emb @ Wi + bi               [16384, 3072]
    {
        dim3 grid(H3 / 128, MM / 128);
        sgemm128<0><<<grid, 256>>>(emb, Wi, bi, xi, MM, H3, HH);
    }
    // 3) GRU scan: single persistent kernel, 128 steps
    {
        dim3 grid(HH / 32, BB / 32);   // (32, 4) = 128 blocks, all co-resident
        gru_scan<<<grid, 192>>>(hidden, mask, xi, whT, bhn, y);
    }
    // 4) critic = relu(y @ W1 + b1)       [16384, 1024]
    {
        dim3 grid(HH / 128, MM / 128);
        sgemm128<1><<<grid, 256>>>(y, W1, b1, critic, MM, HH, HH);
    }
    // 5) value = critic @ W2 + b2  -> out[131072 ..)
    value_kernel<<<MM, 256>>>(critic, W2, b2, out + (size_t)BB * HH);
    // 6) h_out = y[T-1]            -> out[0 .. 131072)
    copy_hout<<<(BB * HH / 4) / 256, 256>>>(y + (size_t)(TT - 1) * BB * HH, out);
}

// round 5
// speedup vs baseline: 1.4709x; 1.4709x over previous
#include <cuda_runtime.h>
#include <cuda_bf16.h>
#include <math.h>

// ---------------------------------------------------------------------------
// CriticRNN: T=128, B=128, OBS=512, H=1024
// ---------------------------------------------------------------------------

#define TT  128
#define BB  128
#define OBS 512
#define HH  1024
#define H3  3072
#define MM  (TT * BB)   // 16384

// Static device scratch (no allocations allowed)
__device__ float g_emb[(size_t)MM * HH];      // 64 MB
__device__ float g_xi[(size_t)MM * H3];       // 192 MB
__device__ float g_y[(size_t)MM * HH];        // 64 MB
__device__ float g_critic[(size_t)MM * HH];   // 64 MB
__device__ float g_mask[MM];                  // keep-mask: 1.0 = keep, 0.0 = reset
__device__ int   g_bytemode;
__device__ unsigned g_bar;                    // grid barrier counter

// ---------------------------------------------------------------------------
// dones layout detection + mask expansion (byte-bool vs int32).
// ---------------------------------------------------------------------------
__global__ void detect_mask_mode(const unsigned int* __restrict__ d)
{
    __shared__ int flag;
    if (threadIdx.x == 0) flag = 0;
    __syncthreads();
    int f = 0;
    for (int i = threadIdx.x; i < MM / 4; i += blockDim.x)
        if (d[i] > 1u) f = 1;
    if (f) atomicOr(&flag, 1);
    __syncthreads();
    if (threadIdx.x == 0) g_bytemode = flag;
}

__global__ void expand_mask(const void* __restrict__ dones, float* __restrict__ mask)
{
    const int i = blockIdx.x * blockDim.x + threadIdx.x;
    if (i >= MM) return;
    int done;
    if (g_bytemode)
        done = ((const unsigned char*)dones)[i] != 0;
    else
        done = ((const int*)dones)[i] != 0;
    mask[i] = done ? 0.f : 1.f;
}

// ---------------------------------------------------------------------------
// fp32 SGEMM, double-buffered smem: C[M,N] = op(A[M,K] @ B[K,N] + bias[N])
// BM=BN=128, BK=8, 256 threads, 8x8 per thread. (At SIMT fp32 ceiling.)
// ---------------------------------------------------------------------------
template <int DO_RELU>
__global__ __launch_bounds__(256, 2)
void sgemm128(const float* __restrict__ A, const float* __restrict__ B,
              const float* __restrict__ bias, float* __restrict__ C,
              int M, int N, int K)
{
    __shared__ float As[2][8][128];
    __shared__ float Bs[2][8][128];

    const int tid  = threadIdx.x;
    const int cRow = blockIdx.y * 128;
    const int cCol = blockIdx.x * 128;

    const int rowA = tid >> 1;
    const int colA = (tid & 1) << 2;
    const int rowB = tid >> 5;
    const int colB = (tid & 31) << 2;

    const int tx = tid & 15;
    const int ty = tid >> 4;

    float acc[8][8];
    #pragma unroll
    for (int i = 0; i < 8; i++)
        #pragma unroll
        for (int j = 0; j < 8; j++) acc[i][j] = 0.f;

    const float* Ap = A + (size_t)(cRow + rowA) * K + colA;
    const float* Bp = B + cCol + colB + (size_t)rowB * N;

    float4 a4 = *(const float4*)(Ap);
    float4 b4 = *(const float4*)(Bp);
    As[0][colA + 0][rowA] = a4.x;
    As[0][colA + 1][rowA] = a4.y;
    As[0][colA + 2][rowA] = a4.z;
    As[0][colA + 3][rowA] = a4.w;
    *(float4*)&Bs[0][rowB][colB] = b4;
    __syncthreads();

    int buf = 0;
    for (int kb = 0; kb < K; kb += 8) {
        const bool more = (kb + 8) < K;
        if (more) {
            a4 = *(const float4*)(Ap + kb + 8);
            b4 = *(const float4*)(Bp + (size_t)(kb + 8) * N);
        }

        #pragma unroll
        for (int k = 0; k < 8; k++) {
            float regM[8], regN[8];
            *(float4*)&regM[0] = *(const float4*)&As[buf][k][ty * 8];
            *(float4*)&regM[4] = *(const float4*)&As[buf][k][ty * 8 + 4];
            *(float4*)&regN[0] = *(const float4*)&Bs[buf][k][tx * 8];
            *(float4*)&regN[4] = *(const float4*)&Bs[buf][k][tx * 8 + 4];
            #pragma unroll
            for (int i = 0; i < 8; i++)
                #pragma unroll
                for (int j = 0; j < 8; j++)
                    acc[i][j] += regM[i] * regN[j];
        }

        if (more) {
            const int nb = buf ^ 1;
            As[nb][colA + 0][rowA] = a4.x;
            As[nb][colA + 1][rowA] = a4.y;
            As[nb][colA + 2][rowA] = a4.z;
            As[nb][colA + 3][rowA] = a4.w;
            *(float4*)&Bs[nb][rowB][colB] = b4;
        }
        buf ^= 1;
        __syncthreads();
    }

    #pragma unroll
    for (int i = 0; i < 8; i++) {
        const int r = cRow + ty * 8 + i;
        #pragma unroll
        for (int j = 0; j < 8; j += 4) {
            const int c = cCol + tx * 8 + j;
            float4 v;
            v.x = acc[i][j + 0] + bias[c + 0];
            v.y = acc[i][j + 1] + bias[c + 1];
            v.z = acc[i][j + 2] + bias[c + 2];
            v.w = acc[i][j + 3] + bias[c + 3];
            if (DO_RELU) {
                v.x = fmaxf(v.x, 0.f); v.y = fmaxf(v.y, 0.f);
                v.z = fmaxf(v.z, 0.f); v.w = fmaxf(v.w, 0.f);
            }
            *(float4*)&C[(size_t)r * N + c] = v;
        }
    }
}

// ---------------------------------------------------------------------------
// Persistent GRU scan: one kernel runs all 128 steps with a software grid
// barrier. 128 blocks (grid 32x4), 384 threads, tile 32 batch x 32 hcols x
// 3 gates, thread = 2 rows x 4 cols x 1 gate (plain FFMA — verified math of
// gru_step2) with double-buffered tile loads (global->reg prefetch).
// ---------------------------------------------------------------------------
struct SmemP {
    float hs[2][32][36];    // [buf][row][k]          stride 144B
    float ws[2][32][100];   // [buf][k][g*32+c]       stride 400B
};
struct SmemE {
    float es[3][32][32];    // gate partials (overlay; used post-compute)
};

__global__ __launch_bounds__(384, 1)
void gru_scan(const float* __restrict__ hidden,
              const float* __restrict__ mask,     // [T*B] keep-mask
              const float* __restrict__ xi,       // [T,B,3H]
              const float* __restrict__ Wh,       // [H][3H]
              const float* __restrict__ bhn,      // [H]
              float* __restrict__ y)              // [T,B,H]
{
    __shared__ __align__(16) unsigned char smraw[sizeof(SmemP)];
    SmemP* sp = (SmemP*)smraw;
    SmemE* se = (SmemE*)smraw;

    const int tid = threadIdx.x;
    const int bn  = blockIdx.x * 32;   // h-column base
    const int bm  = blockIdx.y * 32;   // batch-row base

    // compute mapping: gate g, 2 rows, 4 cols
    const int g   = tid / 128;         // 0..2
    const int t2  = tid % 128;
    const int r0  = (t2 >> 3) << 1;    // rows r0, r0+1
    const int c0  = (t2 & 7) << 2;     // cols c0..c0+3
    const int gc0 = g * 32 + c0;

    // h loader mapping (tid < 256): one float4
    const int lr = tid >> 3;           // 0..31
    const int lk = (tid & 7) << 2;     // 0..28
    const bool hv = (tid < 256);

    // w loader mapping: 2 float4 per thread over 32k x 96cols
    int wk[2], wgc[2];
    const float* wptr[2];
    #pragma unroll
    for (int i = 0; i < 2; i++) {
        const int f  = tid + i * 384;
        wk[i] = f / 24;
        const int c4 = f % 24;
        const int wg = c4 >> 3;
        const int wc = (c4 & 7) << 2;
        wgc[i]  = wg * 32 + wc;
        wptr[i] = Wh + (size_t)wk[i] * H3 + wg * HH + bn + wc;   // + kb*H3 later
    }

    for (int t = 0; t < TT; t++) {
        const float* prev = (t == 0) ? hidden : (y + (size_t)(t - 1) * BB * HH);
        const float* mt   = mask + (size_t)t * BB;
        const float* xi_t = xi + (size_t)t * BB * H3;
        float* out        = y + (size_t)t * BB * HH;

        const float dmask = hv ? mt[bm + lr] : 0.f;
        const float* hRow = hv ? (prev + (size_t)(bm + lr) * HH + lk) : prev;

        // prologue: tile kb=0 into buffer 0
        float4 ph = hv ? *(const float4*)(hRow) : make_float4(0.f, 0.f, 0.f, 0.f);
        float4 pw0 = *(const float4*)(wptr[0]);
        float4 pw1 = *(const float4*)(wptr[1]);
        if (hv) {
            sp->hs[0][lr][lk + 0] = ph.x * dmask;
            sp->hs[0][lr][lk + 1] = ph.y * dmask;
            sp->hs[0][lr][lk + 2] = ph.z * dmask;
            sp->hs[0][lr][lk + 3] = ph.w * dmask;
        }
        *(float4*)&sp->ws[0][wk[0]][wgc[0]] = pw0;
        *(float4*)&sp->ws[0][wk[1]][wgc[1]] = pw1;
        __syncthreads();

        float acc[2][4];
        #pragma unroll
        for (int i = 0; i < 2; i++)
            #pragma unroll
            for (int j = 0; j < 4; j++) acc[i][j] = 0.f;

        int buf = 0;
        #pragma unroll 1
        for (int kb = 0; kb < HH; kb += 32) {
            const bool more = (kb + 32) < HH;
            if (more) {
                if (hv) ph = *(const float4*)(hRow + kb + 32);
                pw0 = *(const float4*)(wptr[0] + (size_t)(kb + 32) * H3);
                pw1 = *(const float4*)(wptr[1] + (size_t)(kb + 32) * H3);
            }

            #pragma unroll
            for (int k4 = 0; k4 < 32; k4 += 4) {
                float4 h0 = *(const float4*)&sp->hs[buf][r0][k4];
                float4 h1 = *(const float4*)&sp->hs[buf][r0 + 1][k4];
                float4 w0 = *(const float4*)&sp->ws[buf][k4 + 0][gc0];
                float4 w1 = *(const float4*)&sp->ws[buf][k4 + 1][gc0];
                float4 w2 = *(const float4*)&sp->ws[buf][k4 + 2][gc0];
                float4 w3 = *(const float4*)&sp->ws[buf][k4 + 3][gc0];

                acc[0][0] = fmaf(h0.x, w0.x, acc[0][0]);
                acc[0][1] = fmaf(h0.x, w0.y, acc[0][1]);
                acc[0][2] = fmaf(h0.x, w0.z, acc[0][2]);
                acc[0][3] = fmaf(h0.x, w0.w, acc[0][3]);
                acc[1][0] = fmaf(h1.x, w0.x, acc[1][0]);
                acc[1][1] = fmaf(h1.x, w0.y, acc[1][1]);
                acc[1][2] = fmaf(h1.x, w0.z, acc[1][2]);
                acc[1][3] = fmaf(h1.x, w0.w, acc[1][3]);

                acc[0][0] = fmaf(h0.y, w1.x, acc[0][0]);
                acc[0][1] = fmaf(h0.y, w1.y, acc[0][1]);
                acc[0][2] = fmaf(h0.y, w1.z, acc[0][2]);
                acc[0][3] = fmaf(h0.y, w1.w, acc[0][3]);
                acc[1][0] = fmaf(h1.y, w1.x, acc[1][0]);
                acc[1][1] = fmaf(h1.y, w1.y, acc[1][1]);
                acc[1][2] = fmaf(h1.y, w1.z, acc[1][2]);
                acc[1][3] = fmaf(h1.y, w1.w, acc[1][3]);

                acc[0][0] = fmaf(h0.z, w2.x, acc[0][0]);
                acc[0][1] = fmaf(h0.z, w2.y, acc[0][1]);
                acc[0][2] = fmaf(h0.z, w2.z, acc[0][2]);
                acc[0][3] = fmaf(h0.z, w2.w, acc[0][3]);
                acc[1][0] = fmaf(h1.z, w2.x, acc[1][0]);
                acc[1][1] = fmaf(h1.z, w2.y, acc[1][1]);
                acc[1][2] = fmaf(h1.z, w2.z, acc[1][2]);
                acc[1][3] = fmaf(h1.z, w2.w, acc[1][3]);

                acc[0][0] = fmaf(h0.w, w3.x, acc[0][0]);
                acc[0][1] = fmaf(h0.w, w3.y, acc[0][1]);
                acc[0][2] = fmaf(h0.w, w3.z, acc[0][2]);
                acc[0][3] = fmaf(h0.w, w3.w, acc[0][3]);
                acc[1][0] = fmaf(h1.w, w3.x, acc[1][0]);
                acc[1][1] = fmaf(h1.w, w3.y, acc[1][1]);
                acc[1][2] = fmaf(h1.w, w3.z, acc[1][2]);
                acc[1][3] = fmaf(h1.w, w3.w, acc[1][3]);
            }

            if (more) {
                const int nb = buf ^ 1;
                if (hv) {
                    sp->hs[nb][lr][lk + 0] = ph.x * dmask;
                    sp->hs[nb][lr][lk + 1] = ph.y * dmask;
                    sp->hs[nb][lr][lk + 2] = ph.z * dmask;
                    sp->hs[nb][lr][lk + 3] = ph.w * dmask;
                }
                *(float4*)&sp->ws[nb][wk[0]][wgc[0]] = pw0;
                *(float4*)&sp->ws[nb][wk[1]][wgc[1]] = pw1;
            }
            __syncthreads();
            buf ^= 1;
        }

        // stash gate sums (overlays tile buffers — compute loop fully synced)
        #pragma unroll
        for (int i = 0; i < 2; i++)
            *(float4*)&se->es[g][r0 + i][c0] = *(float4*)&acc[i][0];
        __syncthreads();

        // epilogue: 1024 outputs over tids < 256 (4 consecutive cols each)
        if (hv) {
            const int b = bm + lr;
            const int j = bn + lk;
            const float mk = dmask;

            float4 aR = *(const float4*)&se->es[0][lr][lk];
            float4 aZ = *(const float4*)&se->es[1][lr][lk];
            float4 aN = *(const float4*)&se->es[2][lr][lk];
            float4 hp = *(const float4*)(prev + (size_t)b * HH + j);
            float4 xr = *(const float4*)(xi_t + (size_t)b * H3 + j);
            float4 xz = *(const float4*)(xi_t + (size_t)b * H3 + HH + j);
            float4 xn = *(const float4*)(xi_t + (size_t)b * H3 + 2 * HH + j);
            float4 bh = *(const float4*)(bhn + j);

            float4 o;
            {
                const float r = 1.f / (1.f + expf(-(xr.x + aR.x)));
                const float z = 1.f / (1.f + expf(-(xz.x + aZ.x)));
                const float n = tanhf(xn.x + r * (aN.x + bh.x));
                o.x = (1.f - z) * n + z * (hp.x * mk);
            }
            {
                const float r = 1.f / (1.f + expf(-(xr.y + aR.y)));
                const float z = 1.f / (1.f + expf(-(xz.y + aZ.y)));
                const float n = tanhf(xn.y + r * (aN.y + bh.y));
                o.y = (1.f - z) * n + z * (hp.y * mk);
            }
            {
                const float r = 1.f / (1.f + expf(-(xr.z + aR.z)));
                const float z = 1.f / (1.f + expf(-(xz.z + aZ.z)));
                const float n = tanhf(xn.z + r * (aN.z + bh.z));
                o.z = (1.f - z) * n + z * (hp.z * mk);
            }
            {
                const float r = 1.f / (1.f + expf(-(xr.w + aR.w)));
                const float z = 1.f / (1.f + expf(-(xz.w + aZ.w)));
                const float n = tanhf(xn.w + r * (aN.w + bh.w));
                o.w = (1.f - z) * n + z * (hp.w * mk);
            }
            *(float4*)(out + (size_t)b * HH + j) = o;
        }

        // grid barrier (skip after last step)
        if (t < TT - 1) {
            __syncthreads();
            if (tid == 0) {
                __threadfence();
                atomicAdd(&g_bar, 1u);
                const unsigned target = (unsigned)(gridDim.x * gridDim.y) * (t + 1);
                while (*((volatile unsigned*)&g_bar) < target) { }
                __threadfence();
            }
            __syncthreads();
        }
    }
}

// ---------------------------------------------------------------------------
// value[m] = sum_j critic[m,j] * W2[j] + b2 ; one block per row m
// ---------------------------------------------------------------------------
__global__ __launch_bounds__(256)
void value_kernel(const float* __restrict__ critic, const float* __restrict__ W2,
                  const float* __restrict__ b2, float* __restrict__ out)
{
    const int m   = blockIdx.x;
    const int tid = threadIdx.x;
    float s = 0.f;
    const float* row = critic + (size_t)m * HH;
    for (int j = tid * 4; j < HH; j += 256 * 4) {
        float4 c4 = *(const float4*)(row + j);
        float4 w4 = *(const float4*)(W2 + j);
        s += c4.x * w4.x + c4.y * w4.y + c4.z * w4.z + c4.w * w4.w;
    }
    #pragma unroll
    for (int off = 16; off > 0; off >>= 1)
        s += __shfl_down_sync(0xffffffffu, s, off);
    __shared__ float red[8];
    if ((tid & 31) == 0) red[tid >> 5] = s;
    __syncthreads();
    if (tid == 0) {
        float t = 0.f;
        #pragma unroll
        for (int w = 0; w < 8; w++) t += red[w];
        out[m] = t + b2[0];
    }
}

__global__ void copy_hout(const float* __restrict__ src, float* __restrict__ dst)
{
    const int i = (blockIdx.x * blockDim.x + threadIdx.x) * 4;
    *(float4*)&dst[i] = *(const float4*)&src[i];
}

// ---------------------------------------------------------------------------
// Launch
// ---------------------------------------------------------------------------
extern "C" void kernel_launch(void* const* d_in, const int* in_sizes, int n_in,
                              void* d_out, int out_size)
{
    const float* hidden = (const float*)d_in[0];
    const float* ws     = (const float*)d_in[1];          // [T,B,OBS]
    const void*  dones  = (const void*)d_in[2];           // [T,B] bool/int32
    const float* W_emb  = (const float*)d_in[3];
    const float* b_emb  = (const float*)d_in[4];
    const float* Wi     = (const float*)d_in[5];
    const float* bi     = (const float*)d_in[6];
    const float* Wh     = (const float*)d_in[7];
    const float* bhn    = (const float*)d_in[8];
    const float* W1     = (const float*)d_in[9];
    const float* b1     = (const float*)d_in[10];
    const float* W2     = (const float*)d_in[11];
    const float* b2     = (const float*)d_in[12];
    float* out = (float*)d_out;

    float *emb, *xi, *y, *critic, *mask;
    unsigned* barp;
    cudaGetSymbolAddress((void**)&emb,    g_emb);
    cudaGetSymbolAddress((void**)&xi,     g_xi);
    cudaGetSymbolAddress((void**)&y,      g_y);
    cudaGetSymbolAddress((void**)&critic, g_critic);
    cudaGetSymbolAddress((void**)&mask,   g_mask);
    cudaGetSymbolAddress((void**)&barp,   g_bar);

    // 0) reset grid barrier; mask detection/expansion
    cudaMemsetAsync(barp, 0, sizeof(unsigned));
    detect_mask_mode<<<1, 256>>>((const unsigned int*)dones);
    expand_mask<<<MM / 256, 256>>>(dones, mask);

    // 1) emb = relu(WS @ W_emb + b_emb)   [16384, 1024]
    {
        dim3 grid(HH / 128, MM / 128);
        sgemm128<1><<<grid, 256>>>(ws, W_emb, b_emb, emb, MM, HH, OBS);
    }
    // 2) xi = emb @ Wi + bi               [16384, 3072]
    {
        dim3 grid(H3 / 128, MM / 128);
        sgemm128<0><<<grid, 256>>>(emb, Wi, bi, xi, MM, H3, HH);
    }
    // 3) GRU scan: single persistent kernel, 128 steps
    {
        dim3 grid(HH / 32, BB / 32);   // (32, 4) = 128 blocks, all co-resident
        gru_scan<<<grid, 384>>>(hidden, mask, xi, Wh, bhn, y);
    }
    // 4) critic = relu(y @ W1 + b1)       [16384, 1024]
    {
        dim3 grid(HH / 128, MM / 128);
        sgemm128<1><<<grid, 256>>>(y, W1, b1, critic, MM, HH, HH);
    }
    // 5) value = critic @ W2 + b2  -> out[131072 ..)
    value_kernel<<<MM, 256>>>(critic, W2, b2, out + (size_t)BB * HH);
    // 6) h_out = y[T-1]            -> out[0 .. 131072)
    copy_hout<<<(BB * HH / 4) / 256, 256>>>(y + (size_t)(TT - 1) * BB * HH, out);
}

// round 7
// speedup vs baseline: 1.4755x; 1.0031x over previous
#include <cuda_runtime.h>
#include <cuda_bf16.h>
#include <math.h>

// ---------------------------------------------------------------------------
// CriticRNN: T=128, B=128, OBS=512, H=1024
// GEMMs via tf32 mma.sync (3xtf32 split, fp32-grade accuracy).
// ---------------------------------------------------------------------------

#define TT  128
#define BB  128
#define OBS 512
#define HH  1024
#define H3  3072
#define MM  (TT * BB)   // 16384

// Static device scratch (no allocations allowed)
__device__ float g_emb[(size_t)MM * HH];      // 64 MB
__device__ float g_xi[(size_t)MM * H3];       // 192 MB
__device__ float g_y[(size_t)MM * HH];        // 64 MB
__device__ float g_critic[(size_t)MM * HH];   // 64 MB
__device__ float g_mask[MM];                  // keep-mask: 1.0 = keep, 0.0 = reset
__device__ int   g_bytemode;
__device__ unsigned g_bar;                    // grid barrier counter

// ---------------------------------------------------------------------------
// dones layout detection + mask expansion (byte-bool vs int32).
// ---------------------------------------------------------------------------
__global__ void detect_mask_mode(const unsigned int* __restrict__ d)
{
    __shared__ int flag;
    if (threadIdx.x == 0) flag = 0;
    __syncthreads();
    int f = 0;
    for (int i = threadIdx.x; i < MM / 4; i += blockDim.x)
        if (d[i] > 1u) f = 1;
    if (f) atomicOr(&flag, 1);
    __syncthreads();
    if (threadIdx.x == 0) g_bytemode = flag;
}

__global__ void expand_mask(const void* __restrict__ dones, float* __restrict__ mask)
{
    const int i = blockIdx.x * blockDim.x + threadIdx.x;
    if (i >= MM) return;
    int done;
    if (g_bytemode)
        done = ((const unsigned char*)dones)[i] != 0;
    else
        done = ((const int*)dones)[i] != 0;
    mask[i] = done ? 0.f : 1.f;
}

// ---------------------------------------------------------------------------
// tf32 helpers
// ---------------------------------------------------------------------------
__device__ __forceinline__ unsigned f2tf(float x)
{
    unsigned u;
    asm("cvt.rna.tf32.f32 %0, %1;" : "=r"(u) : "f"(x));
    return u;
}
__device__ __forceinline__ void tf_split(float x, unsigned& hi, unsigned& lo)
{
    hi = f2tf(x);
    lo = f2tf(x - __uint_as_float(hi));
}
__device__ __forceinline__ void mma_tf32(float* d,
                                         unsigned a0, unsigned a1, unsigned a2, unsigned a3,
                                         unsigned b0, unsigned b1)
{
    asm("mma.sync.aligned.m16n8k8.row.col.f32.tf32.tf32.f32 "
        "{%0,%1,%2,%3}, {%4,%5,%6,%7}, {%8,%9}, {%0,%1,%2,%3};"
        : "+f"(d[0]), "+f"(d[1]), "+f"(d[2]), "+f"(d[3])
        : "r"(a0), "r"(a1), "r"(a2), "r"(a3), "r"(b0), "r"(b1));
}

// ---------------------------------------------------------------------------
// tf32 3x-split tensor-core GEMM: C[M,N] = op(A[M,K] @ B[K,N] + bias[N])
// Block tile 128x128, BK=16, 256 threads = 8 warps (2m x 4n), warp 64x32.
// A/B split hi/lo into smem at staging; fragment LDS conflict-free (pad 136).
// M%128==0, N%128==0, K%16==0.
// ---------------------------------------------------------------------------
#define PAD 136

template <int DO_RELU>
__global__ __launch_bounds__(256, 1)
void mma_gemm(const float* __restrict__ A, const float* __restrict__ B,
              const float* __restrict__ bias, float* __restrict__ C,
              int M, int N, int K)
{
    __shared__ unsigned Ah[16][PAD];
    __shared__ unsigned Al[16][PAD];
    __shared__ unsigned Bh[16][PAD];
    __shared__ unsigned Bl[16][PAD];

    const int tid  = threadIdx.x;
    const int wid  = tid >> 5;
    const int lane = tid & 31;
    const int gid  = lane >> 2;   // 0..7
    const int tig  = lane & 3;    // 0..3

    const int cRow = blockIdx.y * 128;
    const int cCol = blockIdx.x * 128;

    const int warp_m = (wid >> 2) * 64;   // 0 or 64
    const int warp_n = (wid & 3) * 32;    // 0,32,64,96

    // A loader: row = tid>>1 (0..127), 8 k-values at (tid&1)*8
    const int arow = tid >> 1;
    const int acol = (tid & 1) * 8;
    const float* Ap = A + (size_t)(cRow + arow) * K + acol;

    // B loader: krow = tid>>4 (0..15), 8 n-values at (tid&15)*8
    const int bkrow = tid >> 4;
    const int bcol  = (tid & 15) * 8;
    const float* Bp = B + (size_t)bkrow * N + cCol + bcol;

    float acc[4][4][4];
    #pragma unroll
    for (int i = 0; i < 4; i++)
        #pragma unroll
        for (int j = 0; j < 4; j++)
            #pragma unroll
            for (int r = 0; r < 4; r++) acc[i][j][r] = 0.f;

    // prologue: load tile 0 into registers
    float4 a0 = *(const float4*)(Ap);
    float4 a1 = *(const float4*)(Ap + 4);
    float4 b0 = *(const float4*)(Bp);
    float4 b1 = *(const float4*)(Bp + 4);

    for (int kb = 0; kb < K; kb += 16) {
        // stage current tile into smem (split hi/lo)
        {
            float av[8] = {a0.x, a0.y, a0.z, a0.w, a1.x, a1.y, a1.z, a1.w};
            #pragma unroll
            for (int c = 0; c < 8; c++) {
                unsigned hi, lo;
                tf_split(av[c], hi, lo);
                Ah[acol + c][arow] = hi;
                Al[acol + c][arow] = lo;
            }
            unsigned h[8], l[8];
            float bv[8] = {b0.x, b0.y, b0.z, b0.w, b1.x, b1.y, b1.z, b1.w};
            #pragma unroll
            for (int c = 0; c < 8; c++) tf_split(bv[c], h[c], l[c]);
            *(uint4*)&Bh[bkrow][bcol]     = make_uint4(h[0], h[1], h[2], h[3]);
            *(uint4*)&Bh[bkrow][bcol + 4] = make_uint4(h[4], h[5], h[6], h[7]);
            *(uint4*)&Bl[bkrow][bcol]     = make_uint4(l[0], l[1], l[2], l[3]);
            *(uint4*)&Bl[bkrow][bcol + 4] = make_uint4(l[4], l[5], l[6], l[7]);
        }
        __syncthreads();

        // prefetch next tile
        const bool more = (kb + 16) < K;
        if (more) {
            a0 = *(const float4*)(Ap + kb + 16);
            a1 = *(const float4*)(Ap + kb + 16 + 4);
            b0 = *(const float4*)(Bp + (size_t)(kb + 16) * N);
            b1 = *(const float4*)(Bp + (size_t)(kb + 16) * N + 4);
        }

        // compute: two k8 steps
        #pragma unroll
        for (int kk = 0; kk < 16; kk += 8) {
            // B fragments for 4 n-tiles
            unsigned bh[4][2], bl[4][2];
            #pragma unroll
            for (int j = 0; j < 4; j++) {
                const int n0 = warp_n + j * 8 + gid;
                bh[j][0] = Bh[kk + tig][n0];
                bh[j][1] = Bh[kk + tig + 4][n0];
                bl[j][0] = Bl[kk + tig][n0];
                bl[j][1] = Bl[kk + tig + 4][n0];
            }
            #pragma unroll
            for (int i = 0; i < 4; i++) {
                const int r0 = warp_m + i * 16 + gid;
                const unsigned ah0 = Ah[kk + tig][r0];
                const unsigned ah1 = Ah[kk + tig][r0 + 8];
                const unsigned ah2 = Ah[kk + tig + 4][r0];
                const unsigned ah3 = Ah[kk + tig + 4][r0 + 8];
                const unsigned al0 = Al[kk + tig][r0];
                const unsigned al1 = Al[kk + tig][r0 + 8];
                const unsigned al2 = Al[kk + tig + 4][r0];
                const unsigned al3 = Al[kk + tig + 4][r0 + 8];
                #pragma unroll
                for (int j = 0; j < 4; j++) {
                    mma_tf32(acc[i][j], ah0, ah1, ah2, ah3, bh[j][0], bh[j][1]);
                    mma_tf32(acc[i][j], ah0, ah1, ah2, ah3, bl[j][0], bl[j][1]);
                    mma_tf32(acc[i][j], al0, al1, al2, al3, bh[j][0], bh[j][1]);
                }
            }
        }
        __syncthreads();
    }

    // epilogue
    #pragma unroll
    for (int i = 0; i < 4; i++) {
        const int row0 = cRow + warp_m + i * 16 + gid;
        #pragma unroll
        for (int j = 0; j < 4; j++) {
            const int col = cCol + warp_n + j * 8 + tig * 2;
            float2 v0, v1;
            v0.x = acc[i][j][0] + bias[col];
            v0.y = acc[i][j][1] + bias[col + 1];
            v1.x = acc[i][j][2] + bias[col];
            v1.y = acc[i][j][3] + bias[col + 1];
            if (DO_RELU) {
                v0.x = fmaxf(v0.x, 0.f); v0.y = fmaxf(v0.y, 0.f);
                v1.x = fmaxf(v1.x, 0.f); v1.y = fmaxf(v1.y, 0.f);
            }
            *(float2*)&C[(size_t)row0 * N + col]       = v0;
            *(float2*)&C[(size_t)(row0 + 8) * N + col] = v1;
        }
    }
}

// ---------------------------------------------------------------------------
// Persistent GRU scan (unchanged from R5): 128 blocks, 384 threads.
// ---------------------------------------------------------------------------
struct SmemP {
    float hs[2][32][36];
    float ws[2][32][100];
};
struct SmemE {
    float es[3][32][32];
};

__global__ __launch_bounds__(384, 1)
void gru_scan(const float* __restrict__ hidden,
              const float* __restrict__ mask,
              const float* __restrict__ xi,
              const float* __restrict__ Wh,
              const float* __restrict__ bhn,
              float* __restrict__ y)
{
    __shared__ __align__(16) unsigned char smraw[sizeof(SmemP)];
    SmemP* sp = (SmemP*)smraw;
    SmemE* se = (SmemE*)smraw;

    const int tid = threadIdx.x;
    const int bn  = blockIdx.x * 32;
    const int bm  = blockIdx.y * 32;

    const int g   = tid / 128;
    const int t2  = tid % 128;
    const int r0  = (t2 >> 3) << 1;
    const int c0  = (t2 & 7) << 2;
    const int gc0 = g * 32 + c0;

    const int lr = tid >> 3;
    const int lk = (tid & 7) << 2;
    const bool hv = (tid < 256);

    int wk[2], wgc[2];
    const float* wptr[2];
    #pragma unroll
    for (int i = 0; i < 2; i++) {
        const int f  = tid + i * 384;
        wk[i] = f / 24;
        const int c4 = f % 24;
        const int wg = c4 >> 3;
        const int wc = (c4 & 7) << 2;
        wgc[i]  = wg * 32 + wc;
        wptr[i] = Wh + (size_t)wk[i] * H3 + wg * HH + bn + wc;
    }

    for (int t = 0; t < TT; t++) {
        const float* prev = (t == 0) ? hidden : (y + (size_t)(t - 1) * BB * HH);
        const float* mt   = mask + (size_t)t * BB;
        const float* xi_t = xi + (size_t)t * BB * H3;
        float* out        = y + (size_t)t * BB * HH;

        const float dmask = hv ? mt[bm + lr] : 0.f;
        const float* hRow = hv ? (prev + (size_t)(bm + lr) * HH + lk) : prev;

        float4 ph = hv ? *(const float4*)(hRow) : make_float4(0.f, 0.f, 0.f, 0.f);
        float4 pw0 = *(const float4*)(wptr[0]);
        float4 pw1 = *(const float4*)(wptr[1]);
        if (hv) {
            sp->hs[0][lr][lk + 0] = ph.x * dmask;
            sp->hs[0][lr][lk + 1] = ph.y * dmask;
            sp->hs[0][lr][lk + 2] = ph.z * dmask;
            sp->hs[0][lr][lk + 3] = ph.w * dmask;
        }
        *(float4*)&sp->ws[0][wk[0]][wgc[0]] = pw0;
        *(float4*)&sp->ws[0][wk[1]][wgc[1]] = pw1;
        __syncthreads();

        float acc[2][4];
        #pragma unroll
        for (int i = 0; i < 2; i++)
            #pragma unroll
            for (int j = 0; j < 4; j++) acc[i][j] = 0.f;

        int buf = 0;
        #pragma unroll 1
        for (int kb = 0; kb < HH; kb += 32) {
            const bool more = (kb + 32) < HH;
            if (more) {
                if (hv) ph = *(const float4*)(hRow + kb + 32);
                pw0 = *(const float4*)(wptr[0] + (size_t)(kb + 32) * H3);
                pw1 = *(const float4*)(wptr[1] + (size_t)(kb + 32) * H3);
            }

            #pragma unroll
            for (int k4 = 0; k4 < 32; k4 += 4) {
                float4 h0 = *(const float4*)&sp->hs[buf][r0][k4];
                float4 h1 = *(const float4*)&sp->hs[buf][r0 + 1][k4];
                float4 w0 = *(const float4*)&sp->ws[buf][k4 + 0][gc0];
                float4 w1 = *(const float4*)&sp->ws[buf][k4 + 1][gc0];
                float4 w2 = *(const float4*)&sp->ws[buf][k4 + 2][gc0];
                float4 w3 = *(const float4*)&sp->ws[buf][k4 + 3][gc0];

                acc[0][0] = fmaf(h0.x, w0.x, acc[0][0]);
                acc[0][1] = fmaf(h0.x, w0.y, acc[0][1]);
                acc[0][2] = fmaf(h0.x, w0.z, acc[0][2]);
                acc[0][3] = fmaf(h0.x, w0.w, acc[0][3]);
                acc[1][0] = fmaf(h1.x, w0.x, acc[1][0]);
                acc[1][1] = fmaf(h1.x, w0.y, acc[1][1]);
                acc[1][2] = fmaf(h1.x, w0.z, acc[1][2]);
                acc[1][3] = fmaf(h1.x, w0.w, acc[1][3]);

                acc[0][0] = fmaf(h0.y, w1.x, acc[0][0]);
                acc[0][1] = fmaf(h0.y, w1.y, acc[0][1]);
                acc[0][2] = fmaf(h0.y, w1.z, acc[0][2]);
                acc[0][3] = fmaf(h0.y, w1.w, acc[0][3]);
                acc[1][0] = fmaf(h1.y, w1.x, acc[1][0]);
                acc[1][1] = fmaf(h1.y, w1.y, acc[1][1]);
                acc[1][2] = fmaf(h1.y, w1.z, acc[1][2]);
                acc[1][3] = fmaf(h1.y, w1.w, acc[1][3]);

                acc[0][0] = fmaf(h0.z, w2.x, acc[0][0]);
                acc[0][1] = fmaf(h0.z, w2.y, acc[0][1]);
                acc[0][2] = fmaf(h0.z, w2.z, acc[0][2]);
                acc[0][3] = fmaf(h0.z, w2.w, acc[0][3]);
                acc[1][0] = fmaf(h1.z, w2.x, acc[1][0]);
                acc[1][1] = fmaf(h1.z, w2.y, acc[1][1]);
                acc[1][2] = fmaf(h1.z, w2.z, acc[1][2]);
                acc[1][3] = fmaf(h1.z, w2.w, acc[1][3]);

                acc[0][0] = fmaf(h0.w, w3.x, acc[0][0]);
                acc[0][1] = fmaf(h0.w, w3.y, acc[0][1]);
                acc[0][2] = fmaf(h0.w, w3.z, acc[0][2]);
                acc[0][3] = fmaf(h0.w, w3.w, acc[0][3]);
                acc[1][0] = fmaf(h1.w, w3.x, acc[1][0]);
                acc[1][1] = fmaf(h1.w, w3.y, acc[1][1]);
                acc[1][2] = fmaf(h1.w, w3.z, acc[1][2]);
                acc[1][3] = fmaf(h1.w, w3.w, acc[1][3]);
            }

            if (more) {
                const int nb = buf ^ 1;
                if (hv) {
                    sp->hs[nb][lr][lk + 0] = ph.x * dmask;
                    sp->hs[nb][lr][lk + 1] = ph.y * dmask;
                    sp->hs[nb][lr][lk + 2] = ph.z * dmask;
                    sp->hs[nb][lr][lk + 3] = ph.w * dmask;
                }
                *(float4*)&sp->ws[nb][wk[0]][wgc[0]] = pw0;
                *(float4*)&sp->ws[nb][wk[1]][wgc[1]] = pw1;
            }
            __syncthreads();
            buf ^= 1;
        }

        #pragma unroll
        for (int i = 0; i < 2; i++)
            *(float4*)&se->es[g][r0 + i][c0] = *(float4*)&acc[i][0];
        __syncthreads();

        if (hv) {
            const int b = bm + lr;
            const int j = bn + lk;
            const float mk = dmask;

            float4 aR = *(const float4*)&se->es[0][lr][lk];
            float4 aZ = *(const float4*)&se->es[1][lr][lk];
            float4 aN = *(const float4*)&se->es[2][lr][lk];
            float4 hp = *(const float4*)(prev + (size_t)b * HH + j);
            float4 xr = *(const float4*)(xi_t + (size_t)b * H3 + j);
            float4 xz = *(const float4*)(xi_t + (size_t)b * H3 + HH + j);
            float4 xn = *(const float4*)(xi_t + (size_t)b * H3 + 2 * HH + j);
            float4 bh = *(const float4*)(bhn + j);

            float4 o;
            {
                const float r = 1.f / (1.f + expf(-(xr.x + aR.x)));
                const float z = 1.f / (1.f + expf(-(xz.x + aZ.x)));
                const float n = tanhf(xn.x + r * (aN.x + bh.x));
                o.x = (1.f - z) * n + z * (hp.x * mk);
            }
            {
                const float r = 1.f / (1.f + expf(-(xr.y + aR.y)));
                const float z = 1.f / (1.f + expf(-(xz.y + aZ.y)));
                const float n = tanhf(xn.y + r * (aN.y + bh.y));
                o.y = (1.f - z) * n + z * (hp.y * mk);
            }
            {
                const float r = 1.f / (1.f + expf(-(xr.z + aR.z)));
                const float z = 1.f / (1.f + expf(-(xz.z + aZ.z)));
                const float n = tanhf(xn.z + r * (aN.z + bh.z));
                o.z = (1.f - z) * n + z * (hp.z * mk);
            }
            {
                const float r = 1.f / (1.f + expf(-(xr.w + aR.w)));
                const float z = 1.f / (1.f + expf(-(xz.w + aZ.w)));
                const float n = tanhf(xn.w + r * (aN.w + bh.w));
                o.w = (1.f - z) * n + z * (hp.w * mk);
            }
            *(float4*)(out + (size_t)b * HH + j) = o;
        }

        if (t < TT - 1) {
            __syncthreads();
            if (tid == 0) {
                __threadfence();
                atomicAdd(&g_bar, 1u);
                const unsigned target = (unsigned)(gridDim.x * gridDim.y) * (t + 1);
                while (*((volatile unsigned*)&g_bar) < target) { }
                __threadfence();
            }
            __syncthreads();
        }
    }
}

// ---------------------------------------------------------------------------
// value[m] = sum_j critic[m,j] * W2[j] + b2 ; one block per row m
// ---------------------------------------------------------------------------
__global__ __launch_bounds__(256)
void value_kernel(const float* __restrict__ critic, const float* __restrict__ W2,
                  const float* __restrict__ b2, float* __restrict__ out)
{
    const int m   = blockIdx.x;
    const int tid = threadIdx.x;
    float s = 0.f;
    const float* row = critic + (size_t)m * HH;
    for (int j = tid * 4; j < HH; j += 256 * 4) {
        float4 c4 = *(const float4*)(row + j);
        float4 w4 = *(const float4*)(W2 + j);
        s += c4.x * w4.x + c4.y * w4.y + c4.z * w4.z + c4.w * w4.w;
    }
    #pragma unroll
    for (int off = 16; off > 0; off >>= 1)
        s += __shfl_down_sync(0xffffffffu, s, off);
    __shared__ float red[8];
    if ((tid & 31) == 0) red[tid >> 5] = s;
    __syncthreads();
    if (tid == 0) {
        float t = 0.f;
        #pragma unroll
        for (int w = 0; w < 8; w++) t += red[w];
        out[m] = t + b2[0];
    }
}

__global__ void copy_hout(const float* __restrict__ src, float* __restrict__ dst)
{
    const int i = (blockIdx.x * blockDim.x + threadIdx.x) * 4;
    *(float4*)&dst[i] = *(const float4*)&src[i];
}

// ---------------------------------------------------------------------------
// Launch
// ---------------------------------------------------------------------------
extern "C" void kernel_launch(void* const* d_in, const int* in_sizes, int n_in,
                              void* d_out, int out_size)
{
    const float* hidden = (const float*)d_in[0];
    const float* ws     = (const float*)d_in[1];
    const void*  dones  = (const void*)d_in[2];
    const float* W_emb  = (const float*)d_in[3];
    const float* b_emb  = (const float*)d_in[4];
    const float* Wi     = (const float*)d_in[5];
    const float* bi     = (const float*)d_in[6];
    const float* Wh     = (const float*)d_in[7];
    const float* bhn    = (const float*)d_in[8];
    const float* W1     = (const float*)d_in[9];
    const float* b1     = (const float*)d_in[10];
    const float* W2     = (const float*)d_in[11];
    const float* b2     = (const float*)d_in[12];
    float* out = (float*)d_out;

    float *emb, *xi, *y, *critic, *mask;
    unsigned* barp;
    cudaGetSymbolAddress((void**)&emb,    g_emb);
    cudaGetSymbolAddress((void**)&xi,     g_xi);
    cudaGetSymbolAddress((void**)&y,      g_y);
    cudaGetSymbolAddress((void**)&critic, g_critic);
    cudaGetSymbolAddress((void**)&mask,   g_mask);
    cudaGetSymbolAddress((void**)&barp,   g_bar);

    // 0) reset grid barrier; mask detection/expansion
    cudaMemsetAsync(barp, 0, sizeof(unsigned));
    detect_mask_mode<<<1, 256>>>((const unsigned int*)dones);
    expand_mask<<<MM / 256, 256>>>(dones, mask);

    // 1) emb = relu(WS @ W_emb + b_emb)   [16384, 1024]
    {
        dim3 grid(HH / 128, MM / 128);
        mma_gemm<1><<<grid, 256>>>(ws, W_emb, b_emb, emb, MM, HH, OBS);
    }
    // 2) xi = emb @ Wi + bi               [16384, 3072]
    {
        dim3 grid(H3 / 128, MM / 128);
        mma_gemm<0><<<grid, 256>>>(emb, Wi, bi, xi, MM, H3, HH);
    }
    // 3) GRU scan: single persistent kernel, 128 steps
    {
        dim3 grid(HH / 32, BB / 32);
        gru_scan<<<grid, 384>>>(hidden, mask, xi, Wh, bhn, y);
    }
    // 4) critic = relu(y @ W1 + b1)       [16384, 1024]
    {
        dim3 grid(HH / 128, MM / 128);
        mma_gemm<1><<<grid, 256>>>(y, W1, b1, critic, MM, HH, HH);
    }
    // 5) value = critic @ W2 + b2  -> out[131072 ..)
    value_kernel<<<MM, 256>>>(critic, W2, b2, out + (size_t)BB * HH);
    // 6) h_out = y[T-1]            -> out[0 .. 131072)
    copy_hout<<<(BB * HH / 4) / 256, 256>>>(y + (size_t)(TT - 1) * BB * HH, out);
}

// round 9
// speedup vs baseline: 1.9420x; 1.3162x over previous
#include <cuda_runtime.h>
#include <cuda_bf16.h>
#include <math.h>

// ---------------------------------------------------------------------------
// CriticRNN: T=128, B=128, OBS=512, H=1024
// GEMMs + GRU scan via tf32 mma.sync (3xtf32 split, fp32-grade accuracy).
// ---------------------------------------------------------------------------

#define TT  128
#define BB  128
#define OBS 512
#define HH  1024
#define H3  3072
#define MM  (TT * BB)   // 16384
#define COLG 32         // h-column groups (32 cols each)
#define KQ   4          // K split factor in the scan
#define KS   (HH / KQ)  // 256 k per split

// Static device scratch (no allocations allowed)
__device__ float    g_emb[(size_t)MM * HH];      // 64 MB
__device__ float    g_xi[(size_t)MM * H3];       // 192 MB
__device__ float    g_y[(size_t)MM * HH];        // 64 MB
__device__ float    g_critic[(size_t)MM * HH];   // 64 MB
__device__ unsigned g_whh[(size_t)HH * H3];      // 12.6 MB  Wh hi (tf32)
__device__ unsigned g_whl[(size_t)HH * H3];      // 12.6 MB  Wh lo (tf32)
__device__ unsigned g_hh[BB * HH];               // masked h hi
__device__ unsigned g_hl[BB * HH];               // masked h lo
__device__ float    g_hf[BB * HH];               // masked h fp32
__device__ float    g_part[(size_t)KQ * COLG * BB * 96];  // 6.3 MB partials
__device__ float    g_mask[MM];
__device__ int      g_bytemode;
__device__ unsigned g_bar;

// ---------------------------------------------------------------------------
// dones layout detection + mask expansion (byte-bool vs int32).
// ---------------------------------------------------------------------------
__global__ void detect_mask_mode(const unsigned int* __restrict__ d)
{
    __shared__ int flag;
    if (threadIdx.x == 0) flag = 0;
    __syncthreads();
    int f = 0;
    for (int i = threadIdx.x; i < MM / 4; i += blockDim.x)
        if (d[i] > 1u) f = 1;
    if (f) atomicOr(&flag, 1);
    __syncthreads();
    if (threadIdx.x == 0) g_bytemode = flag;
}

__global__ void expand_mask(const void* __restrict__ dones, float* __restrict__ mask)
{
    const int i = blockIdx.x * blockDim.x + threadIdx.x;
    if (i >= MM) return;
    int done;
    if (g_bytemode)
        done = ((const unsigned char*)dones)[i] != 0;
    else
        done = ((const int*)dones)[i] != 0;
    mask[i] = done ? 0.f : 1.f;
}

// ---------------------------------------------------------------------------
// tf32 helpers
// ---------------------------------------------------------------------------
__device__ __forceinline__ unsigned f2tf(float x)
{
    unsigned u;
    asm("cvt.rna.tf32.f32 %0, %1;" : "=r"(u) : "f"(x));
    return u;
}
__device__ __forceinline__ void tf_split(float x, unsigned& hi, unsigned& lo)
{
    hi = f2tf(x);
    lo = f2tf(x - __uint_as_float(hi));
}
__device__ __forceinline__ void mma_tf32(float* d,
                                         unsigned a0, unsigned a1, unsigned a2, unsigned a3,
                                         unsigned b0, unsigned b1)
{
    asm("mma.sync.aligned.m16n8k8.row.col.f32.tf32.tf32.f32 "
        "{%0,%1,%2,%3}, {%4,%5,%6,%7}, {%8,%9}, {%0,%1,%2,%3};"
        : "+f"(d[0]), "+f"(d[1]), "+f"(d[2]), "+f"(d[3])
        : "r"(a0), "r"(a1), "r"(a2), "r"(a3), "r"(b0), "r"(b1));
}

// ---------------------------------------------------------------------------
// Prep: split Wh into tf32 hi/lo once (constant across the scan).
// ---------------------------------------------------------------------------
__global__ void split_wh(const float* __restrict__ Wh)
{
    const size_t i = (size_t)blockIdx.x * blockDim.x + threadIdx.x;
    if (i >= (size_t)HH * H3) return;
    unsigned hi, lo;
    tf_split(Wh[i], hi, lo);
    g_whh[i] = hi;
    g_whl[i] = lo;
}

// Prep: initial masked h (hidden * mask[0]) fp32 + split.
__global__ void init_h(const float* __restrict__ hidden, const float* __restrict__ mask)
{
    const int i = blockIdx.x * blockDim.x + threadIdx.x;
    if (i >= BB * HH) return;
    const float v = hidden[i] * mask[i / HH];
    g_hf[i] = v;
    unsigned hi, lo;
    tf_split(v, hi, lo);
    g_hh[i] = hi;
    g_hl[i] = lo;
}

// ---------------------------------------------------------------------------
// tf32 3x-split tensor-core GEMM (verified in R7): C = op(A@B + bias)
// Block tile 128x128, BK=16, 256 threads = 8 warps (2m x 4n), warp 64x32.
// ---------------------------------------------------------------------------
#define PAD 136

template <int DO_RELU>
__global__ __launch_bounds__(256, 1)
void mma_gemm(const float* __restrict__ A, const float* __restrict__ B,
              const float* __restrict__ bias, float* __restrict__ C,
              int M, int N, int K)
{
    __shared__ unsigned Ah[16][PAD];
    __shared__ unsigned Al[16][PAD];
    __shared__ unsigned Bh[16][PAD];
    __shared__ unsigned Bl[16][PAD];

    const int tid  = threadIdx.x;
    const int wid  = tid >> 5;
    const int lane = tid & 31;
    const int gid  = lane >> 2;
    const int tig  = lane & 3;

    const int cRow = blockIdx.y * 128;
    const int cCol = blockIdx.x * 128;

    const int warp_m = (wid >> 2) * 64;
    const int warp_n = (wid & 3) * 32;

    const int arow = tid >> 1;
    const int acol = (tid & 1) * 8;
    const float* Ap = A + (size_t)(cRow + arow) * K + acol;

    const int bkrow = tid >> 4;
    const int bcol  = (tid & 15) * 8;
    const float* Bp = B + (size_t)bkrow * N + cCol + bcol;

    float acc[4][4][4];
    #pragma unroll
    for (int i = 0; i < 4; i++)
        #pragma unroll
        for (int j = 0; j < 4; j++)
            #pragma unroll
            for (int r = 0; r < 4; r++) acc[i][j][r] = 0.f;

    float4 a0 = *(const float4*)(Ap);
    float4 a1 = *(const float4*)(Ap + 4);
    float4 b0 = *(const float4*)(Bp);
    float4 b1 = *(const float4*)(Bp + 4);

    for (int kb = 0; kb < K; kb += 16) {
        {
            float av[8] = {a0.x, a0.y, a0.z, a0.w, a1.x, a1.y, a1.z, a1.w};
            #pragma unroll
            for (int c = 0; c < 8; c++) {
                unsigned hi, lo;
                tf_split(av[c], hi, lo);
                Ah[acol + c][arow] = hi;
                Al[acol + c][arow] = lo;
            }
            unsigned h[8], l[8];
            float bv[8] = {b0.x, b0.y, b0.z, b0.w, b1.x, b1.y, b1.z, b1.w};
            #pragma unroll
            for (int c = 0; c < 8; c++) tf_split(bv[c], h[c], l[c]);
            *(uint4*)&Bh[bkrow][bcol]     = make_uint4(h[0], h[1], h[2], h[3]);
            *(uint4*)&Bh[bkrow][bcol + 4] = make_uint4(h[4], h[5], h[6], h[7]);
            *(uint4*)&Bl[bkrow][bcol]     = make_uint4(l[0], l[1], l[2], l[3]);
            *(uint4*)&Bl[bkrow][bcol + 4] = make_uint4(l[4], l[5], l[6], l[7]);
        }
        __syncthreads();

        const bool more = (kb + 16) < K;
        if (more) {
            a0 = *(const float4*)(Ap + kb + 16);
            a1 = *(const float4*)(Ap + kb + 16 + 4);
            b0 = *(const float4*)(Bp + (size_t)(kb + 16) * N);
            b1 = *(const float4*)(Bp + (size_t)(kb + 16) * N + 4);
        }

        #pragma unroll
        for (int kk = 0; kk < 16; kk += 8) {
            unsigned bh[4][2], bl[4][2];
            #pragma unroll
            for (int j = 0; j < 4; j++) {
                const int n0 = warp_n + j * 8 + gid;
                bh[j][0] = Bh[kk + tig][n0];
                bh[j][1] = Bh[kk + tig + 4][n0];
                bl[j][0] = Bl[kk + tig][n0];
                bl[j][1] = Bl[kk + tig + 4][n0];
            }
            #pragma unroll
            for (int i = 0; i < 4; i++) {
                const int r0 = warp_m + i * 16 + gid;
                const unsigned ah0 = Ah[kk + tig][r0];
                const unsigned ah1 = Ah[kk + tig][r0 + 8];
                const unsigned ah2 = Ah[kk + tig + 4][r0];
                const unsigned ah3 = Ah[kk + tig + 4][r0 + 8];
                const unsigned al0 = Al[kk + tig][r0];
                const unsigned al1 = Al[kk + tig][r0 + 8];
                const unsigned al2 = Al[kk + tig + 4][r0];
                const unsigned al3 = Al[kk + tig + 4][r0 + 8];
                #pragma unroll
                for (int j = 0; j < 4; j++) {
                    mma_tf32(acc[i][j], ah0, ah1, ah2, ah3, bh[j][0], bh[j][1]);
                    mma_tf32(acc[i][j], ah0, ah1, ah2, ah3, bl[j][0], bl[j][1]);
                    mma_tf32(acc[i][j], al0, al1, al2, al3, bh[j][0], bh[j][1]);
                }
            }
        }
        __syncthreads();
    }

    #pragma unroll
    for (int i = 0; i < 4; i++) {
        const int row0 = cRow + warp_m + i * 16 + gid;
        #pragma unroll
        for (int j = 0; j < 4; j++) {
            const int col = cCol + warp_n + j * 8 + tig * 2;
            float2 v0, v1;
            v0.x = acc[i][j][0] + bias[col];
            v0.y = acc[i][j][1] + bias[col + 1];
            v1.x = acc[i][j][2] + bias[col];
            v1.y = acc[i][j][3] + bias[col + 1];
            if (DO_RELU) {
                v0.x = fmaxf(v0.x, 0.f); v0.y = fmaxf(v0.y, 0.f);
                v1.x = fmaxf(v1.x, 0.f); v1.y = fmaxf(v1.y, 0.f);
            }
            *(float2*)&C[(size_t)row0 * N + col]       = v0;
            *(float2*)&C[(size_t)(row0 + 8) * N + col] = v1;
        }
    }
}

// ---------------------------------------------------------------------------
// Persistent tensor-core GRU scan.
// Grid (COLG=32, KQ=4) = 128 blocks, 256 threads.
// Per step: phase1 = block (c,q) computes partial[q][c] = h[:,qKS:+KS] @
//   Wh[qKS:+KS, {g*H + 32c ..+32, g=0..2}]  -> [128 x 96] fp32 (3x tf32 mma).
// barrier; phase2 = block (c,q) reduces 4 partials for batch rows 32q..,
//   h-cols 32c.., applies GRU gates, writes y[t] and next step's masked h
//   (fp32 + tf32 hi/lo). barrier.
// ---------------------------------------------------------------------------
__global__ __launch_bounds__(256, 1)
void gru_scan_mma(const float* __restrict__ mask,
                  const float* __restrict__ xi,
                  const float* __restrict__ bhn,
                  float* __restrict__ y)
{
    __shared__ unsigned Ah[16][136];
    __shared__ unsigned Al[16][136];
    __shared__ unsigned Bh[16][104];
    __shared__ unsigned Bl[16][104];

    const int tid  = threadIdx.x;
    const int wid  = tid >> 5;
    const int lane = tid & 31;
    const int gid  = lane >> 2;
    const int tig  = lane & 3;

    const int c = blockIdx.x;        // colgroup 0..31
    const int q = blockIdx.y;        // k-quarter 0..3
    const int bn32  = c * 32;
    const int kbase = q * KS;

    const int warp_m = (wid >> 2) * 64;   // 0 / 64
    const int warp_n = (wid & 3) * 24;    // 0,24,48,72

    // A loader: row = tid>>1 (0..127), 8 k at (tid&1)*8
    const int arow = tid >> 1;
    const int acol = (tid & 1) * 8;
    const unsigned* hhp = g_hh + (size_t)arow * HH + kbase + acol;
    const unsigned* hlp = g_hl + (size_t)arow * HH + kbase + acol;

    // B loader: 384 uint4 tasks (16 krows x 24 col-chunks); task f = tid, tid+256
    const int f0 = tid;
    const int kr0 = f0 / 24, c40 = f0 % 24;
    const int bn0 = (c40 >> 3) * 32 + (c40 & 7) * 4;         // col in 0..95
    const size_t boff0 = (size_t)(kbase + kr0) * H3 + (c40 >> 3) * HH + bn32 + (c40 & 7) * 4;
    const int f1 = tid + 256;
    const bool bv1 = (f1 < 384);
    const int kr1 = f1 / 24, c41 = f1 % 24;
    const int bn1 = (c41 >> 3) * 32 + (c41 & 7) * 4;
    const size_t boff1 = bv1 ? ((size_t)(kbase + kr1) * H3 + (c41 >> 3) * HH + bn32 + (c41 & 7) * 4) : 0;

    float* partp = g_part + (size_t)(q * COLG + c) * BB * 96;

    // phase2 mapping: 32 rows x 32 cols, 4 cols per thread
    const int rloc = tid >> 3;            // 0..31
    const int jj   = (tid & 7) * 4;       // 0..28
    const int pb   = q * 32 + rloc;       // batch row
    const int pj   = bn32 + jj;           // h col

    unsigned tgt = 0;

    for (int t = 0; t < TT; t++) {
        // ================= phase 1: mma partials =================
        float acc[4][3][4];
        #pragma unroll
        for (int i = 0; i < 4; i++)
            #pragma unroll
            for (int j = 0; j < 3; j++)
                #pragma unroll
                for (int r = 0; r < 4; r++) acc[i][j][r] = 0.f;

        uint4 pah0 = *(const uint4*)(hhp);
        uint4 pah1 = *(const uint4*)(hhp + 4);
        uint4 pal0 = *(const uint4*)(hlp);
        uint4 pal1 = *(const uint4*)(hlp + 4);
        uint4 pbh0 = *(const uint4*)(g_whh + boff0);
        uint4 pbl0 = *(const uint4*)(g_whl + boff0);
        uint4 pbh1 = bv1 ? *(const uint4*)(g_whh + boff1) : make_uint4(0, 0, 0, 0);
        uint4 pbl1 = bv1 ? *(const uint4*)(g_whl + boff1) : make_uint4(0, 0, 0, 0);

        #pragma unroll 1
        for (int kb = 0; kb < KS; kb += 16) {
            // stage tile
            {
                unsigned ahv[8] = {pah0.x, pah0.y, pah0.z, pah0.w, pah1.x, pah1.y, pah1.z, pah1.w};
                unsigned alv[8] = {pal0.x, pal0.y, pal0.z, pal0.w, pal1.x, pal1.y, pal1.z, pal1.w};
                #pragma unroll
                for (int cc = 0; cc < 8; cc++) {
                    Ah[acol + cc][arow] = ahv[cc];
                    Al[acol + cc][arow] = alv[cc];
                }
                *(uint4*)&Bh[kr0][bn0] = pbh0;
                *(uint4*)&Bl[kr0][bn0] = pbl0;
                if (bv1) {
                    *(uint4*)&Bh[kr1][bn1] = pbh1;
                    *(uint4*)&Bl[kr1][bn1] = pbl1;
                }
            }
            __syncthreads();

            const bool more = (kb + 16) < KS;
            if (more) {
                pah0 = *(const uint4*)(hhp + kb + 16);
                pah1 = *(const uint4*)(hhp + kb + 16 + 4);
                pal0 = *(const uint4*)(hlp + kb + 16);
                pal1 = *(const uint4*)(hlp + kb + 16 + 4);
                pbh0 = *(const uint4*)(g_whh + boff0 + (size_t)(kb + 16) * H3);
                pbl0 = *(const uint4*)(g_whl + boff0 + (size_t)(kb + 16) * H3);
                if (bv1) {
                    pbh1 = *(const uint4*)(g_whh + boff1 + (size_t)(kb + 16) * H3);
                    pbl1 = *(const uint4*)(g_whl + boff1 + (size_t)(kb + 16) * H3);
                }
            }

            #pragma unroll
            for (int kk = 0; kk < 16; kk += 8) {
                unsigned bh[3][2], bl[3][2];
                #pragma unroll
                for (int j = 0; j < 3; j++) {
                    const int n0 = warp_n + j * 8 + gid;
                    bh[j][0] = Bh[kk + tig][n0];
                    bh[j][1] = Bh[kk + tig + 4][n0];
                    bl[j][0] = Bl[kk + tig][n0];
                    bl[j][1] = Bl[kk + tig + 4][n0];
                }
                #pragma unroll
                for (int i = 0; i < 4; i++) {
                    const int r0 = warp_m + i * 16 + gid;
                    const unsigned ah0 = Ah[kk + tig][r0];
                    const unsigned ah1 = Ah[kk + tig][r0 + 8];
                    const unsigned ah2 = Ah[kk + tig + 4][r0];
                    const unsigned ah3 = Ah[kk + tig + 4][r0 + 8];
                    const unsigned al0 = Al[kk + tig][r0];
                    const unsigned al1 = Al[kk + tig][r0 + 8];
                    const unsigned al2 = Al[kk + tig + 4][r0];
                    const unsigned al3 = Al[kk + tig + 4][r0 + 8];
                    #pragma unroll
                    for (int j = 0; j < 3; j++) {
                        mma_tf32(acc[i][j], ah0, ah1, ah2, ah3, bh[j][0], bh[j][1]);
                        mma_tf32(acc[i][j], ah0, ah1, ah2, ah3, bl[j][0], bl[j][1]);
                        mma_tf32(acc[i][j], al0, al1, al2, al3, bh[j][0], bh[j][1]);
                    }
                }
            }
            __syncthreads();
        }

        // write partials [128 x 96]
        #pragma unroll
        for (int i = 0; i < 4; i++) {
            const int row = warp_m + i * 16 + gid;
            #pragma unroll
            for (int j = 0; j < 3; j++) {
                const int col = warp_n + j * 8 + tig * 2;
                *(float2*)&partp[(size_t)row * 96 + col] =
                    make_float2(acc[i][j][0], acc[i][j][1]);
                *(float2*)&partp[(size_t)(row + 8) * 96 + col] =
                    make_float2(acc[i][j][2], acc[i][j][3]);
            }
        }

        // barrier A
        tgt += 128;
        __syncthreads();
        if (tid == 0) {
            __threadfence();
            atomicAdd(&g_bar, 1u);
            while (*((volatile unsigned*)&g_bar) < tgt) { }
            __threadfence();
        }
        __syncthreads();

        // ================= phase 2: reduce + gates =================
        {
            float4 aR = make_float4(0.f, 0.f, 0.f, 0.f);
            float4 aZ = make_float4(0.f, 0.f, 0.f, 0.f);
            float4 aN = make_float4(0.f, 0.f, 0.f, 0.f);
            #pragma unroll
            for (int qq = 0; qq < KQ; qq++) {
                const float* pp = g_part + ((size_t)(qq * COLG + c) * BB + pb) * 96;
                float4 r4 = *(const float4*)&pp[jj];
                float4 z4 = *(const float4*)&pp[32 + jj];
                float4 n4 = *(const float4*)&pp[64 + jj];
                aR.x += r4.x; aR.y += r4.y; aR.z += r4.z; aR.w += r4.w;
                aZ.x += z4.x; aZ.y += z4.y; aZ.z += z4.z; aZ.w += z4.w;
                aN.x += n4.x; aN.y += n4.y; aN.z += n4.z; aN.w += n4.w;
            }

            const float* xi_t = xi + (size_t)t * BB * H3 + (size_t)pb * H3;
            float4 xr = *(const float4*)(xi_t + pj);
            float4 xz = *(const float4*)(xi_t + HH + pj);
            float4 xn = *(const float4*)(xi_t + 2 * HH + pj);
            float4 hp = *(const float4*)(g_hf + (size_t)pb * HH + pj);
            float4 bh = *(const float4*)(bhn + pj);

            float4 o;
            {
                const float r = 1.f / (1.f + expf(-(xr.x + aR.x)));
                const float z = 1.f / (1.f + expf(-(xz.x + aZ.x)));
                const float n = tanhf(xn.x + r * (aN.x + bh.x));
                o.x = (1.f - z) * n + z * hp.x;
            }
            {
                const float r = 1.f / (1.f + expf(-(xr.y + aR.y)));
                const float z = 1.f / (1.f + expf(-(xz.y + aZ.y)));
                const float n = tanhf(xn.y + r * (aN.y + bh.y));
                o.y = (1.f - z) * n + z * hp.y;
            }
            {
                const float r = 1.f / (1.f + expf(-(xr.z + aR.z)));
                const float z = 1.f / (1.f + expf(-(xz.z + aZ.z)));
                const float n = tanhf(xn.z + r * (aN.z + bh.z));
                o.z = (1.f - z) * n + z * hp.z;
            }
            {
                const float r = 1.f / (1.f + expf(-(xr.w + aR.w)));
                const float z = 1.f / (1.f + expf(-(xz.w + aZ.w)));
                const float n = tanhf(xn.w + r * (aN.w + bh.w));
                o.w = (1.f - z) * n + z * hp.w;
            }
            *(float4*)(y + (size_t)t * BB * HH + (size_t)pb * HH + pj) = o;

            if (t < TT - 1) {
                const float mk = mask[(size_t)(t + 1) * BB + pb];
                float4 hm = make_float4(o.x * mk, o.y * mk, o.z * mk, o.w * mk);
                *(float4*)(g_hf + (size_t)pb * HH + pj) = hm;
                uint4 uh, ul;
                tf_split(hm.x, uh.x, ul.x);
                tf_split(hm.y, uh.y, ul.y);
                tf_split(hm.z, uh.z, ul.z);
                tf_split(hm.w, uh.w, ul.w);
                *(uint4*)(g_hh + (size_t)pb * HH + pj) = uh;
                *(uint4*)(g_hl + (size_t)pb * HH + pj) = ul;
            }
        }

        // barrier B (skip after final step)
        if (t < TT - 1) {
            tgt += 128;
            __syncthreads();
            if (tid == 0) {
                __threadfence();
                atomicAdd(&g_bar, 1u);
                while (*((volatile unsigned*)&g_bar) < tgt) { }
                __threadfence();
            }
            __syncthreads();
        }
    }
}

// ---------------------------------------------------------------------------
// value[m] = sum_j critic[m,j] * W2[j] + b2 ; one block per row m
// ---------------------------------------------------------------------------
__global__ __launch_bounds__(256)
void value_kernel(const float* __restrict__ critic, const float* __restrict__ W2,
                  const float* __restrict__ b2, float* __restrict__ out)
{
    const int m   = blockIdx.x;
    const int tid = threadIdx.x;
    float s = 0.f;
    const float* row = critic + (size_t)m * HH;
    for (int j = tid * 4; j < HH; j += 256 * 4) {
        float4 c4 = *(const float4*)(row + j);
        float4 w4 = *(const float4*)(W2 + j);
        s += c4.x * w4.x + c4.y * w4.y + c4.z * w4.z + c4.w * w4.w;
    }
    #pragma unroll
    for (int off = 16; off > 0; off >>= 1)
        s += __shfl_down_sync(0xffffffffu, s, off);
    __shared__ float red[8];
    if ((tid & 31) == 0) red[tid >> 5] = s;
    __syncthreads();
    if (tid == 0) {
        float t = 0.f;
        #pragma unroll
        for (int w = 0; w < 8; w++) t += red[w];
        out[m] = t + b2[0];
    }
}

__global__ void copy_hout(const float* __restrict__ src, float* __restrict__ dst)
{
    const int i = (blockIdx.x * blockDim.x + threadIdx.x) * 4;
    *(float4*)&dst[i] = *(const float4*)&src[i];
}

// ---------------------------------------------------------------------------
// Launch
// ---------------------------------------------------------------------------
extern "C" void kernel_launch(void* const* d_in, const int* in_sizes, int n_in,
                              void* d_out, int out_size)
{
    const float* hidden = (const float*)d_in[0];
    const float* ws     = (const float*)d_in[1];
    const void*  dones  = (const void*)d_in[2];
    const float* W_emb  = (const float*)d_in[3];
    const float* b_emb  = (const float*)d_in[4];
    const float* Wi     = (const float*)d_in[5];
    const float* bi     = (const float*)d_in[6];
    const float* Wh     = (const float*)d_in[7];
    const float* bhn    = (const float*)d_in[8];
    const float* W1     = (const float*)d_in[9];
    const float* b1     = (const float*)d_in[10];
    const float* W2     = (const float*)d_in[11];
    const float* b2     = (const float*)d_in[12];
    float* out = (float*)d_out;

    float *emb, *xi, *y, *critic, *mask;
    unsigned* barp;
    cudaGetSymbolAddress((void**)&emb,    g_emb);
    cudaGetSymbolAddress((void**)&xi,     g_xi);
    cudaGetSymbolAddress((void**)&y,      g_y);
    cudaGetSymbolAddress((void**)&critic, g_critic);
    cudaGetSymbolAddress((void**)&mask,   g_mask);
    cudaGetSymbolAddress((void**)&barp,   g_bar);

    // 0) barrier reset; mask; weight/state prep
    cudaMemsetAsync(barp, 0, sizeof(unsigned));
    detect_mask_mode<<<1, 256>>>((const unsigned int*)dones);
    expand_mask<<<MM / 256, 256>>>(dones, mask);
    split_wh<<<(int)(((size_t)HH * H3) / 256), 256>>>(Wh);
    init_h<<<(BB * HH) / 256, 256>>>(hidden, mask);

    // 1) emb = relu(WS @ W_emb + b_emb)
    {
        dim3 grid(HH / 128, MM / 128);
        mma_gemm<1><<<grid, 256>>>(ws, W_emb, b_emb, emb, MM, HH, OBS);
    }
    // 2) xi = emb @ Wi + bi
    {
        dim3 grid(H3 / 128, MM / 128);
        mma_gemm<0><<<grid, 256>>>(emb, Wi, bi, xi, MM, H3, HH);
    }
    // 3) GRU scan: persistent tensor-core kernel
    {
        dim3 grid(COLG, KQ);   // 128 blocks
        gru_scan_mma<<<grid, 256>>>(mask, xi, bhn, y);
    }
    // 4) critic = relu(y @ W1 + b1)
    {
        dim3 grid(HH / 128, MM / 128);
        mma_gemm<1><<<grid, 256>>>(y, W1, b1, critic, MM, HH, HH);
    }
    // 5) value -> out[131072 ..)
    value_kernel<<<MM, 256>>>(critic, W2, b2, out + (size_t)BB * HH);
    // 6) h_out = y[T-1] -> out[0 .. 131072)
    copy_hout<<<(BB * HH / 4) / 256, 256>>>(y + (size_t)(TT - 1) * BB * HH, out);
}

// round 10
// speedup vs baseline: 2.1409x; 1.1025x over previous
#include <cuda_runtime.h>
#include <cuda_bf16.h>
#include <math.h>

// ---------------------------------------------------------------------------
// CriticRNN: T=128, B=128, OBS=512, H=1024
// GEMMs + GRU scan via tf32 mma.sync (3xtf32 split), double-buffered staging.
// ---------------------------------------------------------------------------

#define TT  128
#define BB  128
#define OBS 512
#define HH  1024
#define H3  3072
#define MM  (TT * BB)   // 16384
#define COLG 32         // h-column groups (32 cols each)
#define KQ   4          // K split factor in the scan
#define KS   (HH / KQ)  // 256 k per split

// Static device scratch (no allocations allowed)
__device__ float    g_emb[(size_t)MM * HH];      // 64 MB
__device__ float    g_xi[(size_t)MM * H3];       // 192 MB
__device__ float    g_y[(size_t)MM * HH];        // 64 MB
__device__ float    g_critic[(size_t)MM * HH];   // 64 MB
__device__ unsigned g_whh[(size_t)HH * H3];      // 12.6 MB  Wh hi (tf32)
__device__ unsigned g_whl[(size_t)HH * H3];      // 12.6 MB  Wh lo (tf32)
__device__ unsigned g_hh[BB * HH];               // masked h hi
__device__ unsigned g_hl[BB * HH];               // masked h lo
__device__ float    g_hf[BB * HH];               // masked h fp32
__device__ float    g_part[(size_t)KQ * COLG * BB * 96];  // 6.3 MB partials
__device__ float    g_mask[MM];
__device__ int      g_bytemode;
__device__ unsigned g_bar;

// ---------------------------------------------------------------------------
// dones layout detection + mask expansion (byte-bool vs int32).
// ---------------------------------------------------------------------------
__global__ void detect_mask_mode(const unsigned int* __restrict__ d)
{
    __shared__ int flag;
    if (threadIdx.x == 0) flag = 0;
    __syncthreads();
    int f = 0;
    for (int i = threadIdx.x; i < MM / 4; i += blockDim.x)
        if (d[i] > 1u) f = 1;
    if (f) atomicOr(&flag, 1);
    __syncthreads();
    if (threadIdx.x == 0) g_bytemode = flag;
}

__global__ void expand_mask(const void* __restrict__ dones, float* __restrict__ mask)
{
    const int i = blockIdx.x * blockDim.x + threadIdx.x;
    if (i >= MM) return;
    int done;
    if (g_bytemode)
        done = ((const unsigned char*)dones)[i] != 0;
    else
        done = ((const int*)dones)[i] != 0;
    mask[i] = done ? 0.f : 1.f;
}

// ---------------------------------------------------------------------------
// tf32 helpers
// ---------------------------------------------------------------------------
__device__ __forceinline__ unsigned f2tf(float x)
{
    unsigned u;
    asm("cvt.rna.tf32.f32 %0, %1;" : "=r"(u) : "f"(x));
    return u;
}
__device__ __forceinline__ void tf_split(float x, unsigned& hi, unsigned& lo)
{
    hi = f2tf(x);
    lo = f2tf(x - __uint_as_float(hi));
}
__device__ __forceinline__ void mma_tf32(float* d,
                                         unsigned a0, unsigned a1, unsigned a2, unsigned a3,
                                         unsigned b0, unsigned b1)
{
    asm("mma.sync.aligned.m16n8k8.row.col.f32.tf32.tf32.f32 "
        "{%0,%1,%2,%3}, {%4,%5,%6,%7}, {%8,%9}, {%0,%1,%2,%3};"
        : "+f"(d[0]), "+f"(d[1]), "+f"(d[2]), "+f"(d[3])
        : "r"(a0), "r"(a1), "r"(a2), "r"(a3), "r"(b0), "r"(b1));
}

// ---------------------------------------------------------------------------
// Prep: split Wh into tf32 hi/lo once (constant across the scan).
// ---------------------------------------------------------------------------
__global__ void split_wh(const float* __restrict__ Wh)
{
    const size_t i = (size_t)blockIdx.x * blockDim.x + threadIdx.x;
    if (i >= (size_t)HH * H3) return;
    unsigned hi, lo;
    tf_split(Wh[i], hi, lo);
    g_whh[i] = hi;
    g_whl[i] = lo;
}

// Prep: initial masked h (hidden * mask[0]) fp32 + split.
__global__ void init_h(const float* __restrict__ hidden, const float* __restrict__ mask)
{
    const int i = blockIdx.x * blockDim.x + threadIdx.x;
    if (i >= BB * HH) return;
    const float v = hidden[i] * mask[i / HH];
    g_hf[i] = v;
    unsigned hi, lo;
    tf_split(v, hi, lo);
    g_hh[i] = hi;
    g_hl[i] = lo;
}

// ---------------------------------------------------------------------------
// tf32 3x-split tensor-core GEMM, double-buffered: C = op(A@B + bias)
// Block tile 128x128, BK=8, 256 threads = 8 warps (2m x 4n), warp 64x32.
// One __syncthreads per k-tile: prefetch(regs) -> compute(buf) -> stage(buf^1).
// ---------------------------------------------------------------------------
#define PAD 136

template <int DO_RELU>
__global__ __launch_bounds__(256, 1)
void mma_gemm(const float* __restrict__ A, const float* __restrict__ B,
              const float* __restrict__ bias, float* __restrict__ C,
              int M, int N, int K)
{
    __shared__ unsigned Ah[2][8][PAD];
    __shared__ unsigned Al[2][8][PAD];
    __shared__ unsigned Bh[2][8][PAD];
    __shared__ unsigned Bl[2][8][PAD];

    const int tid  = threadIdx.x;
    const int wid  = tid >> 5;
    const int lane = tid & 31;
    const int gid  = lane >> 2;
    const int tig  = lane & 3;

    const int cRow = blockIdx.y * 128;
    const int cCol = blockIdx.x * 128;

    const int warp_m = (wid >> 2) * 64;
    const int warp_n = (wid & 3) * 32;

    // A loader: row = tid>>1 (0..127), 4 k at (tid&1)*4
    const int arow = tid >> 1;
    const int acol = (tid & 1) * 4;
    const float* Ap = A + (size_t)(cRow + arow) * K + acol;

    // B loader: krow = tid>>5 (0..7), 4 n at (tid&31)*4
    const int bkrow = tid >> 5;
    const int bcol  = (tid & 31) * 4;
    const float* Bp = B + (size_t)bkrow * N + cCol + bcol;

    float acc[4][4][4];
    #pragma unroll
    for (int i = 0; i < 4; i++)
        #pragma unroll
        for (int j = 0; j < 4; j++)
            #pragma unroll
            for (int r = 0; r < 4; r++) acc[i][j][r] = 0.f;

    // prologue: stage tile 0 into buffer 0
    float4 a4 = *(const float4*)(Ap);
    float4 b4 = *(const float4*)(Bp);
    {
        float av[4] = {a4.x, a4.y, a4.z, a4.w};
        #pragma unroll
        for (int c = 0; c < 4; c++) {
            unsigned hi, lo;
            tf_split(av[c], hi, lo);
            Ah[0][acol + c][arow] = hi;
            Al[0][acol + c][arow] = lo;
        }
        float bv[4] = {b4.x, b4.y, b4.z, b4.w};
        unsigned h[4], l[4];
        #pragma unroll
        for (int c = 0; c < 4; c++) tf_split(bv[c], h[c], l[c]);
        *(uint4*)&Bh[0][bkrow][bcol] = make_uint4(h[0], h[1], h[2], h[3]);
        *(uint4*)&Bl[0][bkrow][bcol] = make_uint4(l[0], l[1], l[2], l[3]);
    }
    __syncthreads();

    int buf = 0;
    for (int kb = 0; kb < K; kb += 8) {
        const bool more = (kb + 8) < K;
        if (more) {
            a4 = *(const float4*)(Ap + kb + 8);
            b4 = *(const float4*)(Bp + (size_t)(kb + 8) * N);
        }

        // compute on buf (one k8 step)
        {
            unsigned bh[4][2], bl[4][2];
            #pragma unroll
            for (int j = 0; j < 4; j++) {
                const int n0 = warp_n + j * 8 + gid;
                bh[j][0] = Bh[buf][tig][n0];
                bh[j][1] = Bh[buf][tig + 4][n0];
                bl[j][0] = Bl[buf][tig][n0];
                bl[j][1] = Bl[buf][tig + 4][n0];
            }
            #pragma unroll
            for (int i = 0; i < 4; i++) {
                const int r0 = warp_m + i * 16 + gid;
                const unsigned ah0 = Ah[buf][tig][r0];
                const unsigned ah1 = Ah[buf][tig][r0 + 8];
                const unsigned ah2 = Ah[buf][tig + 4][r0];
                const unsigned ah3 = Ah[buf][tig + 4][r0 + 8];
                const unsigned al0 = Al[buf][tig][r0];
                const unsigned al1 = Al[buf][tig][r0 + 8];
                const unsigned al2 = Al[buf][tig + 4][r0];
                const unsigned al3 = Al[buf][tig + 4][r0 + 8];
                #pragma unroll
                for (int j = 0; j < 4; j++) {
                    mma_tf32(acc[i][j], ah0, ah1, ah2, ah3, bh[j][0], bh[j][1]);
                    mma_tf32(acc[i][j], ah0, ah1, ah2, ah3, bl[j][0], bl[j][1]);
                    mma_tf32(acc[i][j], al0, al1, al2, al3, bh[j][0], bh[j][1]);
                }
            }
        }

        // stage next tile into buf^1 (read two iterations ago -> safe)
        if (more) {
            const int nb = buf ^ 1;
            float av[4] = {a4.x, a4.y, a4.z, a4.w};
            #pragma unroll
            for (int c = 0; c < 4; c++) {
                unsigned hi, lo;
                tf_split(av[c], hi, lo);
                Ah[nb][acol + c][arow] = hi;
                Al[nb][acol + c][arow] = lo;
            }
            float bv[4] = {b4.x, b4.y, b4.z, b4.w};
            unsigned h[4], l[4];
            #pragma unroll
            for (int c = 0; c < 4; c++) tf_split(bv[c], h[c], l[c]);
            *(uint4*)&Bh[nb][bkrow][bcol] = make_uint4(h[0], h[1], h[2], h[3]);
            *(uint4*)&Bl[nb][bkrow][bcol] = make_uint4(l[0], l[1], l[2], l[3]);
        }
        __syncthreads();
        buf ^= 1;
    }

    // epilogue
    #pragma unroll
    for (int i = 0; i < 4; i++) {
        const int row0 = cRow + warp_m + i * 16 + gid;
        #pragma unroll
        for (int j = 0; j < 4; j++) {
            const int col = cCol + warp_n + j * 8 + tig * 2;
            float2 v0, v1;
            v0.x = acc[i][j][0] + bias[col];
            v0.y = acc[i][j][1] + bias[col + 1];
            v1.x = acc[i][j][2] + bias[col];
            v1.y = acc[i][j][3] + bias[col + 1];
            if (DO_RELU) {
                v0.x = fmaxf(v0.x, 0.f); v0.y = fmaxf(v0.y, 0.f);
                v1.x = fmaxf(v1.x, 0.f); v1.y = fmaxf(v1.y, 0.f);
            }
            *(float2*)&C[(size_t)row0 * N + col]       = v0;
            *(float2*)&C[(size_t)(row0 + 8) * N + col] = v1;
        }
    }
}

// ---------------------------------------------------------------------------
// Persistent tensor-core GRU scan, double-buffered phase-1 staging.
// Grid (COLG=32, KQ=4) = 128 blocks, 256 threads. BK=8, one sync per k-tile.
// Inputs h (hi/lo) and Wh (hi/lo) are pre-split -> staging has no cvt.
// ---------------------------------------------------------------------------
__global__ __launch_bounds__(256, 1)
void gru_scan_mma(const float* __restrict__ mask,
                  const float* __restrict__ xi,
                  const float* __restrict__ bhn,
                  float* __restrict__ y)
{
    __shared__ unsigned Ah[2][8][136];
    __shared__ unsigned Al[2][8][136];
    __shared__ unsigned Bh[2][8][104];
    __shared__ unsigned Bl[2][8][104];

    const int tid  = threadIdx.x;
    const int wid  = tid >> 5;
    const int lane = tid & 31;
    const int gid  = lane >> 2;
    const int tig  = lane & 3;

    const int c = blockIdx.x;        // colgroup 0..31
    const int q = blockIdx.y;        // k-quarter 0..3
    const int bn32  = c * 32;
    const int kbase = q * KS;

    const int warp_m = (wid >> 2) * 64;   // 0 / 64
    const int warp_n = (wid & 3) * 24;    // 0,24,48,72

    // A loader: row = tid>>1 (0..127), 4 k at (tid&1)*4
    const int arow = tid >> 1;
    const int acol = (tid & 1) * 4;
    const unsigned* hhp = g_hh + (size_t)arow * HH + kbase + acol;
    const unsigned* hlp = g_hl + (size_t)arow * HH + kbase + acol;

    // B loader: 192 uint4 tasks (8 krows x 24 col-chunks), tid < 192
    const bool bv = (tid < 192);
    const int kr = tid / 24, c4 = tid % 24;
    const int bn0 = (c4 >> 3) * 32 + (c4 & 7) * 4;
    const size_t boff = (size_t)(kbase + kr) * H3 + (c4 >> 3) * HH + bn32 + (c4 & 7) * 4;

    float* partp = g_part + (size_t)(q * COLG + c) * BB * 96;

    // phase2 mapping: 32 rows x 32 cols, 4 cols per thread
    const int rloc = tid >> 3;
    const int jj   = (tid & 7) * 4;
    const int pb   = q * 32 + rloc;
    const int pj   = bn32 + jj;

    unsigned tgt = 0;

    for (int t = 0; t < TT; t++) {
        // ================= phase 1: mma partials =================
        float acc[4][3][4];
        #pragma unroll
        for (int i = 0; i < 4; i++)
            #pragma unroll
            for (int j = 0; j < 3; j++)
                #pragma unroll
                for (int r = 0; r < 4; r++) acc[i][j][r] = 0.f;

        uint4 pah = *(const uint4*)(hhp);
        uint4 pal = *(const uint4*)(hlp);
        uint4 pbh = bv ? *(const uint4*)(g_whh + boff) : make_uint4(0, 0, 0, 0);
        uint4 pbl = bv ? *(const uint4*)(g_whl + boff) : make_uint4(0, 0, 0, 0);

        // prologue: stage tile 0 into buffer 0
        {
            unsigned ahv[4] = {pah.x, pah.y, pah.z, pah.w};
            unsigned alv[4] = {pal.x, pal.y, pal.z, pal.w};
            #pragma unroll
            for (int cc = 0; cc < 4; cc++) {
                Ah[0][acol + cc][arow] = ahv[cc];
                Al[0][acol + cc][arow] = alv[cc];
            }
            if (bv) {
                *(uint4*)&Bh[0][kr][bn0] = pbh;
                *(uint4*)&Bl[0][kr][bn0] = pbl;
            }
        }
        __syncthreads();

        int buf = 0;
        #pragma unroll 1
        for (int kb = 0; kb < KS; kb += 8) {
            const bool more = (kb + 8) < KS;
            if (more) {
                pah = *(const uint4*)(hhp + kb + 8);
                pal = *(const uint4*)(hlp + kb + 8);
                if (bv) {
                    pbh = *(const uint4*)(g_whh + boff + (size_t)(kb + 8) * H3);
                    pbl = *(const uint4*)(g_whl + boff + (size_t)(kb + 8) * H3);
                }
            }

            // compute on buf (one k8 step)
            {
                unsigned bh[3][2], bl[3][2];
                #pragma unroll
                for (int j = 0; j < 3; j++) {
                    const int n0 = warp_n + j * 8 + gid;
                    bh[j][0] = Bh[buf][tig][n0];
                    bh[j][1] = Bh[buf][tig + 4][n0];
                    bl[j][0] = Bl[buf][tig][n0];
                    bl[j][1] = Bl[buf][tig + 4][n0];
                }
                #pragma unroll
                for (int i = 0; i < 4; i++) {
                    const int r0 = warp_m + i * 16 + gid;
                    const unsigned ah0 = Ah[buf][tig][r0];
                    const unsigned ah1 = Ah[buf][tig][r0 + 8];
                    const unsigned ah2 = Ah[buf][tig + 4][r0];
                    const unsigned ah3 = Ah[buf][tig + 4][r0 + 8];
                    const unsigned al0 = Al[buf][tig][r0];
                    const unsigned al1 = Al[buf][tig][r0 + 8];
                    const unsigned al2 = Al[buf][tig + 4][r0];
                    const unsigned al3 = Al[buf][tig + 4][r0 + 8];
                    #pragma unroll
                    for (int j = 0; j < 3; j++) {
                        mma_tf32(acc[i][j], ah0, ah1, ah2, ah3, bh[j][0], bh[j][1]);
                        mma_tf32(acc[i][j], ah0, ah1, ah2, ah3, bl[j][0], bl[j][1]);
                        mma_tf32(acc[i][j], al0, al1, al2, al3, bh[j][0], bh[j][1]);
                    }
                }
            }

            // stage next tile into buf^1
            if (more) {
                const int nb = buf ^ 1;
                unsigned ahv[4] = {pah.x, pah.y, pah.z, pah.w};
                unsigned alv[4] = {pal.x, pal.y, pal.z, pal.w};
                #pragma unroll
                for (int cc = 0; cc < 4; cc++) {
                    Ah[nb][acol + cc][arow] = ahv[cc];
                    Al[nb][acol + cc][arow] = alv[cc];
                }
                if (bv) {
                    *(uint4*)&Bh[nb][kr][bn0] = pbh;
                    *(uint4*)&Bl[nb][kr][bn0] = pbl;
                }
            }
            __syncthreads();
            buf ^= 1;
        }

        // write partials [128 x 96]
        #pragma unroll
        for (int i = 0; i < 4; i++) {
            const int row = warp_m + i * 16 + gid;
            #pragma unroll
            for (int j = 0; j < 3; j++) {
                const int col = warp_n + j * 8 + tig * 2;
                *(float2*)&partp[(size_t)row * 96 + col] =
                    make_float2(acc[i][j][0], acc[i][j][1]);
                *(float2*)&partp[(size_t)(row + 8) * 96 + col] =
                    make_float2(acc[i][j][2], acc[i][j][3]);
            }
        }

        // barrier A
        tgt += 128;
        __syncthreads();
        if (tid == 0) {
            __threadfence();
            atomicAdd(&g_bar, 1u);
            while (*((volatile unsigned*)&g_bar) < tgt) { }
            __threadfence();
        }
        __syncthreads();

        // ================= phase 2: reduce + gates =================
        {
            float4 aR = make_float4(0.f, 0.f, 0.f, 0.f);
            float4 aZ = make_float4(0.f, 0.f, 0.f, 0.f);
            float4 aN = make_float4(0.f, 0.f, 0.f, 0.f);
            #pragma unroll
            for (int qq = 0; qq < KQ; qq++) {
                const float* pp = g_part + ((size_t)(qq * COLG + c) * BB + pb) * 96;
                float4 r4 = *(const float4*)&pp[jj];
                float4 z4 = *(const float4*)&pp[32 + jj];
                float4 n4 = *(const float4*)&pp[64 + jj];
                aR.x += r4.x; aR.y += r4.y; aR.z += r4.z; aR.w += r4.w;
                aZ.x += z4.x; aZ.y += z4.y; aZ.z += z4.z; aZ.w += z4.w;
                aN.x += n4.x; aN.y += n4.y; aN.z += n4.z; aN.w += n4.w;
            }

            const float* xi_t = xi + (size_t)t * BB * H3 + (size_t)pb * H3;
            float4 xr = *(const float4*)(xi_t + pj);
            float4 xz = *(const float4*)(xi_t + HH + pj);
            float4 xn = *(const float4*)(xi_t + 2 * HH + pj);
            float4 hp = *(const float4*)(g_hf + (size_t)pb * HH + pj);
            float4 bh = *(const float4*)(bhn + pj);

            float4 o;
            {
                const float r = 1.f / (1.f + expf(-(xr.x + aR.x)));
                const float z = 1.f / (1.f + expf(-(xz.x + aZ.x)));
                const float n = tanhf(xn.x + r * (aN.x + bh.x));
                o.x = (1.f - z) * n + z * hp.x;
            }
            {
                const float r = 1.f / (1.f + expf(-(xr.y + aR.y)));
                const float z = 1.f / (1.f + expf(-(xz.y + aZ.y)));
                const float n = tanhf(xn.y + r * (aN.y + bh.y));
                o.y = (1.f - z) * n + z * hp.y;
            }
            {
                const float r = 1.f / (1.f + expf(-(xr.z + aR.z)));
                const float z = 1.f / (1.f + expf(-(xz.z + aZ.z)));
                const float n = tanhf(xn.z + r * (aN.z + bh.z));
                o.z = (1.f - z) * n + z * hp.z;
            }
            {
                const float r = 1.f / (1.f + expf(-(xr.w + aR.w)));
                const float z = 1.f / (1.f + expf(-(xz.w + aZ.w)));
                const float n = tanhf(xn.w + r * (aN.w + bh.w));
                o.w = (1.f - z) * n + z * hp.w;
            }
            *(float4*)(y + (size_t)t * BB * HH + (size_t)pb * HH + pj) = o;

            if (t < TT - 1) {
                const float mk = mask[(size_t)(t + 1) * BB + pb];
                float4 hm = make_float4(o.x * mk, o.y * mk, o.z * mk, o.w * mk);
                *(float4*)(g_hf + (size_t)pb * HH + pj) = hm;
                uint4 uh, ul;
                tf_split(hm.x, uh.x, ul.x);
                tf_split(hm.y, uh.y, ul.y);
                tf_split(hm.z, uh.z, ul.z);
                tf_split(hm.w, uh.w, ul.w);
                *(uint4*)(g_hh + (size_t)pb * HH + pj) = uh;
                *(uint4*)(g_hl + (size_t)pb * HH + pj) = ul;
            }
        }

        // barrier B (skip after final step)
        if (t < TT - 1) {
            tgt += 128;
            __syncthreads();
            if (tid == 0) {
                __threadfence();
                atomicAdd(&g_bar, 1u);
                while (*((volatile unsigned*)&g_bar) < tgt) { }
                __threadfence();
            }
            __syncthreads();
        }
    }
}

// ---------------------------------------------------------------------------
// value[m] = sum_j critic[m,j] * W2[j] + b2 ; one block per row m
// ---------------------------------------------------------------------------
__global__ __launch_bounds__(256)
void value_kernel(const float* __restrict__ critic, const float* __restrict__ W2,
                  const float* __restrict__ b2, float* __restrict__ out)
{
    const int m   = blockIdx.x;
    const int tid = threadIdx.x;
    float s = 0.f;
    const float* row = critic + (size_t)m * HH;
    for (int j = tid * 4; j < HH; j += 256 * 4) {
        float4 c4 = *(const float4*)(row + j);
        float4 w4 = *(const float4*)(W2 + j);
        s += c4.x * w4.x + c4.y * w4.y + c4.z * w4.z + c4.w * w4.w;
    }
    #pragma unroll
    for (int off = 16; off > 0; off >>= 1)
        s += __shfl_down_sync(0xffffffffu, s, off);
    __shared__ float red[8];
    if ((tid & 31) == 0) red[tid >> 5] = s;
    __syncthreads();
    if (tid == 0) {
        float t = 0.f;
        #pragma unroll
        for (int w = 0; w < 8; w++) t += red[w];
        out[m] = t + b2[0];
    }
}

__global__ void copy_hout(const float* __restrict__ src, float* __restrict__ dst)
{
    const int i = (blockIdx.x * blockDim.x + threadIdx.x) * 4;
    *(float4*)&dst[i] = *(const float4*)&src[i];
}

// ---------------------------------------------------------------------------
// Launch
// ---------------------------------------------------------------------------
extern "C" void kernel_launch(void* const* d_in, const int* in_sizes, int n_in,
                              void* d_out, int out_size)
{
    const float* hidden = (const float*)d_in[0];
    const float* ws     = (const float*)d_in[1];
    const void*  dones  = (const void*)d_in[2];
    const float* W_emb  = (const float*)d_in[3];
    const float* b_emb  = (const float*)d_in[4];
    const float* Wi     = (const float*)d_in[5];
    const float* bi     = (const float*)d_in[6];
    const float* Wh     = (const float*)d_in[7];
    const float* bhn    = (const float*)d_in[8];
    const float* W1     = (const float*)d_in[9];
    const float* b1     = (const float*)d_in[10];
    const float* W2     = (const float*)d_in[11];
    const float* b2     = (const float*)d_in[12];
    float* out = (float*)d_out;

    float *emb, *xi, *y, *critic, *mask;
    unsigned* barp;
    cudaGetSymbolAddress((void**)&emb,    g_emb);
    cudaGetSymbolAddress((void**)&xi,     g_xi);
    cudaGetSymbolAddress((void**)&y,      g_y);
    cudaGetSymbolAddress((void**)&critic, g_critic);
    cudaGetSymbolAddress((void**)&mask,   g_mask);
    cudaGetSymbolAddress((void**)&barp,   g_bar);

    // 0) barrier reset; mask; weight/state prep
    cudaMemsetAsync(barp, 0, sizeof(unsigned));
    detect_mask_mode<<<1, 256>>>((const unsigned int*)dones);
    expand_mask<<<MM / 256, 256>>>(dones, mask);
    split_wh<<<(int)(((size_t)HH * H3) / 256), 256>>>(Wh);
    init_h<<<(BB * HH) / 256, 256>>>(hidden, mask);

    // 1) emb = relu(WS @ W_emb + b_emb)
    {
        dim3 grid(HH / 128, MM / 128);
        mma_gemm<1><<<grid, 256>>>(ws, W_emb, b_emb, emb, MM, HH, OBS);
    }
    // 2) xi = emb @ Wi + bi
    {
        dim3 grid(H3 / 128, MM / 128);
        mma_gemm<0><<<grid, 256>>>(emb, Wi, bi, xi, MM, H3, HH);
    }
    // 3) GRU scan: persistent tensor-core kernel
    {
        dim3 grid(COLG, KQ);   // 128 blocks
        gru_scan_mma<<<grid, 256>>>(mask, xi, bhn, y);
    }
    // 4) critic = relu(y @ W1 + b1)
    {
        dim3 grid(HH / 128, MM / 128);
        mma_gemm<1><<<grid, 256>>>(y, W1, b1, critic, MM, HH, HH);
    }
    // 5) value -> out[131072 ..)
    value_kernel<<<MM, 256>>>(critic, W2, b2, out + (size_t)BB * HH);
    // 6) h_out = y[T-1] -> out[0 .. 131072)
    copy_hout<<<(BB * HH / 4) / 256, 256>>>(y + (size_t)(TT - 1) * BB * HH, out);
}

// round 11
// speedup vs baseline: 2.3301x; 1.0884x over previous
#include <cuda_runtime.h>
#include <cuda_bf16.h>
#include <math.h>

// ---------------------------------------------------------------------------
// CriticRNN: T=128, B=128, OBS=512, H=1024
// GEMMs + GRU scan via tf32 mma.sync (3xtf32 split), double-buffered staging,
// pre-split constant weights, 2 blocks/SM on the GEMMs.
// ---------------------------------------------------------------------------

#define TT  128
#define BB  128
#define OBS 512
#define HH  1024
#define H3  3072
#define MM  (TT * BB)   // 16384
#define COLG 32         // h-column groups (32 cols each)
#define KQ   4          // K split factor in the scan
#define KS   (HH / KQ)  // 256 k per split

// Static device scratch (no allocations allowed)
__device__ float    g_emb[(size_t)MM * HH];      // 64 MB
__device__ float    g_xi[(size_t)MM * H3];       // 192 MB
__device__ float    g_y[(size_t)MM * HH];        // 64 MB
__device__ float    g_critic[(size_t)MM * HH];   // 64 MB
__device__ unsigned g_whh[(size_t)HH * H3];      // 12.6 MB  Wh hi (tf32)
__device__ unsigned g_whl[(size_t)HH * H3];      // 12.6 MB  Wh lo (tf32)
__device__ unsigned g_wembh[(size_t)OBS * HH];   // 2.1 MB   W_emb hi
__device__ unsigned g_wembl[(size_t)OBS * HH];   // 2.1 MB   W_emb lo
__device__ unsigned g_wih[(size_t)HH * H3];      // 12.6 MB  Wi hi
__device__ unsigned g_wil[(size_t)HH * H3];      // 12.6 MB  Wi lo
__device__ unsigned g_w1h[(size_t)HH * HH];      // 4.2 MB   W1 hi
__device__ unsigned g_w1l[(size_t)HH * HH];      // 4.2 MB   W1 lo
__device__ unsigned g_hh[BB * HH];               // masked h hi
__device__ unsigned g_hl[BB * HH];               // masked h lo
__device__ float    g_hf[BB * HH];               // masked h fp32
__device__ float    g_part[(size_t)KQ * COLG * BB * 96];  // 6.3 MB partials
__device__ float    g_mask[MM];
__device__ int      g_bytemode;
__device__ unsigned g_bar;

// ---------------------------------------------------------------------------
// dones layout detection + mask expansion (byte-bool vs int32).
// ---------------------------------------------------------------------------
__global__ void detect_mask_mode(const unsigned int* __restrict__ d)
{
    __shared__ int flag;
    if (threadIdx.x == 0) flag = 0;
    __syncthreads();
    int f = 0;
    for (int i = threadIdx.x; i < MM / 4; i += blockDim.x)
        if (d[i] > 1u) f = 1;
    if (f) atomicOr(&flag, 1);
    __syncthreads();
    if (threadIdx.x == 0) g_bytemode = flag;
}

__global__ void expand_mask(const void* __restrict__ dones, float* __restrict__ mask)
{
    const int i = blockIdx.x * blockDim.x + threadIdx.x;
    if (i >= MM) return;
    int done;
    if (g_bytemode)
        done = ((const unsigned char*)dones)[i] != 0;
    else
        done = ((const int*)dones)[i] != 0;
    mask[i] = done ? 0.f : 1.f;
}

// ---------------------------------------------------------------------------
// tf32 helpers
// ---------------------------------------------------------------------------
__device__ __forceinline__ unsigned f2tf(float x)
{
    unsigned u;
    asm("cvt.rna.tf32.f32 %0, %1;" : "=r"(u) : "f"(x));
    return u;
}
__device__ __forceinline__ void tf_split(float x, unsigned& hi, unsigned& lo)
{
    hi = f2tf(x);
    lo = f2tf(x - __uint_as_float(hi));
}
__device__ __forceinline__ void mma_tf32(float* d,
                                         unsigned a0, unsigned a1, unsigned a2, unsigned a3,
                                         unsigned b0, unsigned b1)
{
    asm("mma.sync.aligned.m16n8k8.row.col.f32.tf32.tf32.f32 "
        "{%0,%1,%2,%3}, {%4,%5,%6,%7}, {%8,%9}, {%0,%1,%2,%3};"
        : "+f"(d[0]), "+f"(d[1]), "+f"(d[2]), "+f"(d[3])
        : "r"(a0), "r"(a1), "r"(a2), "r"(a3), "r"(b0), "r"(b1));
}

// ---------------------------------------------------------------------------
// Prep: split a matrix into tf32 hi/lo (constant weights, done once).
// ---------------------------------------------------------------------------
__global__ void split_mat(const float* __restrict__ src,
                          unsigned* __restrict__ hi_out,
                          unsigned* __restrict__ lo_out, int n)
{
    const int i = blockIdx.x * blockDim.x + threadIdx.x;
    if (i >= n) return;
    unsigned hi, lo;
    tf_split(src[i], hi, lo);
    hi_out[i] = hi;
    lo_out[i] = lo;
}

// Prep: initial masked h (hidden * mask[0]) fp32 + split.
__global__ void init_h(const float* __restrict__ hidden, const float* __restrict__ mask)
{
    const int i = blockIdx.x * blockDim.x + threadIdx.x;
    if (i >= BB * HH) return;
    const float v = hidden[i] * mask[i / HH];
    g_hf[i] = v;
    unsigned hi, lo;
    tf_split(v, hi, lo);
    g_hh[i] = hi;
    g_hl[i] = lo;
}

// ---------------------------------------------------------------------------
// tf32 3x-split tensor-core GEMM, double-buffered, pre-split B:
//   C = op(A@B + bias),  B given as tf32 hi/lo planes.
// Block tile 128x128, BK=8, 256 threads = 8 warps (2m x 4n), warp 64x32.
// 2 blocks/SM (69.6 KB smem total, regs capped at 128).
// ---------------------------------------------------------------------------
#define PAD 136

template <int DO_RELU>
__global__ __launch_bounds__(256, 2)
void mma_gemm(const float* __restrict__ A,
              const unsigned* __restrict__ Bhg, const unsigned* __restrict__ Blg,
              const float* __restrict__ bias, float* __restrict__ C,
              int M, int N, int K)
{
    __shared__ unsigned Ah[2][8][PAD];
    __shared__ unsigned Al[2][8][PAD];
    __shared__ unsigned Bh[2][8][PAD];
    __shared__ unsigned Bl[2][8][PAD];

    const int tid  = threadIdx.x;
    const int wid  = tid >> 5;
    const int lane = tid & 31;
    const int gid  = lane >> 2;
    const int tig  = lane & 3;

    const int cRow = blockIdx.y * 128;
    const int cCol = blockIdx.x * 128;

    const int warp_m = (wid >> 2) * 64;
    const int warp_n = (wid & 3) * 32;

    // A loader: row = tid>>1 (0..127), 4 k at (tid&1)*4
    const int arow = tid >> 1;
    const int acol = (tid & 1) * 4;
    const float* Ap = A + (size_t)(cRow + arow) * K + acol;

    // B loader: krow = tid>>5 (0..7), 4 n at (tid&31)*4 — pure uint4 copies
    const int bkrow = tid >> 5;
    const int bcol  = (tid & 31) * 4;
    const unsigned* Bph = Bhg + (size_t)bkrow * N + cCol + bcol;
    const unsigned* Bpl = Blg + (size_t)bkrow * N + cCol + bcol;

    float acc[4][4][4];
    #pragma unroll
    for (int i = 0; i < 4; i++)
        #pragma unroll
        for (int j = 0; j < 4; j++)
            #pragma unroll
            for (int r = 0; r < 4; r++) acc[i][j][r] = 0.f;

    // prologue: stage tile 0 into buffer 0
    float4 a4 = *(const float4*)(Ap);
    uint4 bh4 = *(const uint4*)(Bph);
    uint4 bl4 = *(const uint4*)(Bpl);
    {
        float av[4] = {a4.x, a4.y, a4.z, a4.w};
        #pragma unroll
        for (int c = 0; c < 4; c++) {
            unsigned hi, lo;
            tf_split(av[c], hi, lo);
            Ah[0][acol + c][arow] = hi;
            Al[0][acol + c][arow] = lo;
        }
        *(uint4*)&Bh[0][bkrow][bcol] = bh4;
        *(uint4*)&Bl[0][bkrow][bcol] = bl4;
    }
    __syncthreads();

    int buf = 0;
    for (int kb = 0; kb < K; kb += 8) {
        const bool more = (kb + 8) < K;
        if (more) {
            a4  = *(const float4*)(Ap + kb + 8);
            bh4 = *(const uint4*)(Bph + (size_t)(kb + 8) * N);
            bl4 = *(const uint4*)(Bpl + (size_t)(kb + 8) * N);
        }

        // compute on buf (one k8 step)
        {
            unsigned bh[4][2], bl[4][2];
            #pragma unroll
            for (int j = 0; j < 4; j++) {
                const int n0 = warp_n + j * 8 + gid;
                bh[j][0] = Bh[buf][tig][n0];
                bh[j][1] = Bh[buf][tig + 4][n0];
                bl[j][0] = Bl[buf][tig][n0];
                bl[j][1] = Bl[buf][tig + 4][n0];
            }
            #pragma unroll
            for (int i = 0; i < 4; i++) {
                const int r0 = warp_m + i * 16 + gid;
                const unsigned ah0 = Ah[buf][tig][r0];
                const unsigned ah1 = Ah[buf][tig][r0 + 8];
                const unsigned ah2 = Ah[buf][tig + 4][r0];
                const unsigned ah3 = Ah[buf][tig + 4][r0 + 8];
                const unsigned al0 = Al[buf][tig][r0];
                const unsigned al1 = Al[buf][tig][r0 + 8];
                const unsigned al2 = Al[buf][tig + 4][r0];
                const unsigned al3 = Al[buf][tig + 4][r0 + 8];
                #pragma unroll
                for (int j = 0; j < 4; j++) {
                    mma_tf32(acc[i][j], ah0, ah1, ah2, ah3, bh[j][0], bh[j][1]);
                    mma_tf32(acc[i][j], ah0, ah1, ah2, ah3, bl[j][0], bl[j][1]);
                    mma_tf32(acc[i][j], al0, al1, al2, al3, bh[j][0], bh[j][1]);
                }
            }
        }

        // stage next tile into buf^1
        if (more) {
            const int nb = buf ^ 1;
            float av[4] = {a4.x, a4.y, a4.z, a4.w};
            #pragma unroll
            for (int c = 0; c < 4; c++) {
                unsigned hi, lo;
                tf_split(av[c], hi, lo);
                Ah[nb][acol + c][arow] = hi;
                Al[nb][acol + c][arow] = lo;
            }
            *(uint4*)&Bh[nb][bkrow][bcol] = bh4;
            *(uint4*)&Bl[nb][bkrow][bcol] = bl4;
        }
        __syncthreads();
        buf ^= 1;
    }

    // epilogue
    #pragma unroll
    for (int i = 0; i < 4; i++) {
        const int row0 = cRow + warp_m + i * 16 + gid;
        #pragma unroll
        for (int j = 0; j < 4; j++) {
            const int col = cCol + warp_n + j * 8 + tig * 2;
            float2 v0, v1;
            v0.x = acc[i][j][0] + bias[col];
            v0.y = acc[i][j][1] + bias[col + 1];
            v1.x = acc[i][j][2] + bias[col];
            v1.y = acc[i][j][3] + bias[col + 1];
            if (DO_RELU) {
                v0.x = fmaxf(v0.x, 0.f); v0.y = fmaxf(v0.y, 0.f);
                v1.x = fmaxf(v1.x, 0.f); v1.y = fmaxf(v1.y, 0.f);
            }
            *(float2*)&C[(size_t)row0 * N + col]       = v0;
            *(float2*)&C[(size_t)(row0 + 8) * N + col] = v1;
        }
    }
}

// ---------------------------------------------------------------------------
// Persistent tensor-core GRU scan, double-buffered phase-1 staging.
// Grid (COLG=32, KQ=4) = 128 blocks, 256 threads. BK=8, one sync per k-tile.
// Inputs h (hi/lo) and Wh (hi/lo) are pre-split -> staging has no cvt.
// ---------------------------------------------------------------------------
__global__ __launch_bounds__(256, 1)
void gru_scan_mma(const float* __restrict__ mask,
                  const float* __restrict__ xi,
                  const float* __restrict__ bhn,
                  float* __restrict__ y)
{
    __shared__ unsigned Ah[2][8][136];
    __shared__ unsigned Al[2][8][136];
    __shared__ unsigned Bh[2][8][104];
    __shared__ unsigned Bl[2][8][104];

    const int tid  = threadIdx.x;
    const int wid  = tid >> 5;
    const int lane = tid & 31;
    const int gid  = lane >> 2;
    const int tig  = lane & 3;

    const int c = blockIdx.x;        // colgroup 0..31
    const int q = blockIdx.y;        // k-quarter 0..3
    const int bn32  = c * 32;
    const int kbase = q * KS;

    const int warp_m = (wid >> 2) * 64;   // 0 / 64
    const int warp_n = (wid & 3) * 24;    // 0,24,48,72

    // A loader: row = tid>>1 (0..127), 4 k at (tid&1)*4
    const int arow = tid >> 1;
    const int acol = (tid & 1) * 4;
    const unsigned* hhp = g_hh + (size_t)arow * HH + kbase + acol;
    const unsigned* hlp = g_hl + (size_t)arow * HH + kbase + acol;

    // B loader: 192 uint4 tasks (8 krows x 24 col-chunks), tid < 192
    const bool bv = (tid < 192);
    const int kr = tid / 24, c4 = tid % 24;
    const int bn0 = (c4 >> 3) * 32 + (c4 & 7) * 4;
    const size_t boff = (size_t)(kbase + kr) * H3 + (c4 >> 3) * HH + bn32 + (c4 & 7) * 4;

    float* partp = g_part + (size_t)(q * COLG + c) * BB * 96;

    // phase2 mapping: 32 rows x 32 cols, 4 cols per thread
    const int rloc = tid >> 3;
    const int jj   = (tid & 7) * 4;
    const int pb   = q * 32 + rloc;
    const int pj   = bn32 + jj;

    unsigned tgt = 0;

    for (int t = 0; t < TT; t++) {
        // ================= phase 1: mma partials =================
        float acc[4][3][4];
        #pragma unroll
        for (int i = 0; i < 4; i++)
            #pragma unroll
            for (int j = 0; j < 3; j++)
                #pragma unroll
                for (int r = 0; r < 4; r++) acc[i][j][r] = 0.f;

        uint4 pah = *(const uint4*)(hhp);
        uint4 pal = *(const uint4*)(hlp);
        uint4 pbh = bv ? *(const uint4*)(g_whh + boff) : make_uint4(0, 0, 0, 0);
        uint4 pbl = bv ? *(const uint4*)(g_whl + boff) : make_uint4(0, 0, 0, 0);

        // prologue: stage tile 0 into buffer 0
        {
            unsigned ahv[4] = {pah.x, pah.y, pah.z, pah.w};
            unsigned alv[4] = {pal.x, pal.y, pal.z, pal.w};
            #pragma unroll
            for (int cc = 0; cc < 4; cc++) {
                Ah[0][acol + cc][arow] = ahv[cc];
                Al[0][acol + cc][arow] = alv[cc];
            }
            if (bv) {
                *(uint4*)&Bh[0][kr][bn0] = pbh;
                *(uint4*)&Bl[0][kr][bn0] = pbl;
            }
        }
        __syncthreads();

        int buf = 0;
        #pragma unroll 1
        for (int kb = 0; kb < KS; kb += 8) {
            const bool more = (kb + 8) < KS;
            if (more) {
                pah = *(const uint4*)(hhp + kb + 8);
                pal = *(const uint4*)(hlp + kb + 8);
                if (bv) {
                    pbh = *(const uint4*)(g_whh + boff + (size_t)(kb + 8) * H3);
                    pbl = *(const uint4*)(g_whl + boff + (size_t)(kb + 8) * H3);
                }
            }

            // compute on buf (one k8 step)
            {
                unsigned bh[3][2], bl[3][2];
                #pragma unroll
                for (int j = 0; j < 3; j++) {
                    const int n0 = warp_n + j * 8 + gid;
                    bh[j][0] = Bh[buf][tig][n0];
                    bh[j][1] = Bh[buf][tig + 4][n0];
                    bl[j][0] = Bl[buf][tig][n0];
                    bl[j][1] = Bl[buf][tig + 4][n0];
                }
                #pragma unroll
                for (int i = 0; i < 4; i++) {
                    const int r0 = warp_m + i * 16 + gid;
                    const unsigned ah0 = Ah[buf][tig][r0];
                    const unsigned ah1 = Ah[buf][tig][r0 + 8];
                    const unsigned ah2 = Ah[buf][tig + 4][r0];
                    const unsigned ah3 = Ah[buf][tig + 4][r0 + 8];
                    const unsigned al0 = Al[buf][tig][r0];
                    const unsigned al1 = Al[buf][tig][r0 + 8];
                    const unsigned al2 = Al[buf][tig + 4][r0];
                    const unsigned al3 = Al[buf][tig + 4][r0 + 8];
                    #pragma unroll
                    for (int j = 0; j < 3; j++) {
                        mma_tf32(acc[i][j], ah0, ah1, ah2, ah3, bh[j][0], bh[j][1]);
                        mma_tf32(acc[i][j], ah0, ah1, ah2, ah3, bl[j][0], bl[j][1]);
                        mma_tf32(acc[i][j], al0, al1, al2, al3, bh[j][0], bh[j][1]);
                    }
                }
            }

            // stage next tile into buf^1
            if (more) {
                const int nb = buf ^ 1;
                unsigned ahv[4] = {pah.x, pah.y, pah.z, pah.w};
                unsigned alv[4] = {pal.x, pal.y, pal.z, pal.w};
                #pragma unroll
                for (int cc = 0; cc < 4; cc++) {
                    Ah[nb][acol + cc][arow] = ahv[cc];
                    Al[nb][acol + cc][arow] = alv[cc];
                }
                if (bv) {
                    *(uint4*)&Bh[nb][kr][bn0] = pbh;
                    *(uint4*)&Bl[nb][kr][bn0] = pbl;
                }
            }
            __syncthreads();
            buf ^= 1;
        }

        // write partials [128 x 96]
        #pragma unroll
        for (int i = 0; i < 4; i++) {
            const int row = warp_m + i * 16 + gid;
            #pragma unroll
            for (int j = 0; j < 3; j++) {
                const int col = warp_n + j * 8 + tig * 2;
                *(float2*)&partp[(size_t)row * 96 + col] =
                    make_float2(acc[i][j][0], acc[i][j][1]);
                *(float2*)&partp[(size_t)(row + 8) * 96 + col] =
                    make_float2(acc[i][j][2], acc[i][j][3]);
            }
        }

        // barrier A
        tgt += 128;
        __syncthreads();
        if (tid == 0) {
            __threadfence();
            atomicAdd(&g_bar, 1u);
            while (*((volatile unsigned*)&g_bar) < tgt) { }
            __threadfence();
        }
        __syncthreads();

        // ================= phase 2: reduce + gates =================
        {
            float4 aR = make_float4(0.f, 0.f, 0.f, 0.f);
            float4 aZ = make_float4(0.f, 0.f, 0.f, 0.f);
            float4 aN = make_float4(0.f, 0.f, 0.f, 0.f);
            #pragma unroll
            for (int qq = 0; qq < KQ; qq++) {
                const float* pp = g_part + ((size_t)(qq * COLG + c) * BB + pb) * 96;
                float4 r4 = *(const float4*)&pp[jj];
                float4 z4 = *(const float4*)&pp[32 + jj];
                float4 n4 = *(const float4*)&pp[64 + jj];
                aR.x += r4.x; aR.y += r4.y; aR.z += r4.z; aR.w += r4.w;
                aZ.x += z4.x; aZ.y += z4.y; aZ.z += z4.z; aZ.w += z4.w;
                aN.x += n4.x; aN.y += n4.y; aN.z += n4.z; aN.w += n4.w;
            }

            const float* xi_t = xi + (size_t)t * BB * H3 + (size_t)pb * H3;
            float4 xr = *(const float4*)(xi_t + pj);
            float4 xz = *(const float4*)(xi_t + HH + pj);
            float4 xn = *(const float4*)(xi_t + 2 * HH + pj);
            float4 hp = *(const float4*)(g_hf + (size_t)pb * HH + pj);
            float4 bh = *(const float4*)(bhn + pj);

            float4 o;
            {
                const float r = 1.f / (1.f + expf(-(xr.x + aR.x)));
                const float z = 1.f / (1.f + expf(-(xz.x + aZ.x)));
                const float n = tanhf(xn.x + r * (aN.x + bh.x));
                o.x = (1.f - z) * n + z * hp.x;
            }
            {
                const float r = 1.f / (1.f + expf(-(xr.y + aR.y)));
                const float z = 1.f / (1.f + expf(-(xz.y + aZ.y)));
                const float n = tanhf(xn.y + r * (aN.y + bh.y));
                o.y = (1.f - z) * n + z * hp.y;
            }
            {
                const float r = 1.f / (1.f + expf(-(xr.z + aR.z)));
                const float z = 1.f / (1.f + expf(-(xz.z + aZ.z)));
                const float n = tanhf(xn.z + r * (aN.z + bh.z));
                o.z = (1.f - z) * n + z * hp.z;
            }
            {
                const float r = 1.f / (1.f + expf(-(xr.w + aR.w)));
                const float z = 1.f / (1.f + expf(-(xz.w + aZ.w)));
                const float n = tanhf(xn.w + r * (aN.w + bh.w));
                o.w = (1.f - z) * n + z * hp.w;
            }
            *(float4*)(y + (size_t)t * BB * HH + (size_t)pb * HH + pj) = o;

            if (t < TT - 1) {
                const float mk = mask[(size_t)(t + 1) * BB + pb];
                float4 hm = make_float4(o.x * mk, o.y * mk, o.z * mk, o.w * mk);
                *(float4*)(g_hf + (size_t)pb * HH + pj) = hm;
                uint4 uh, ul;
                tf_split(hm.x, uh.x, ul.x);
                tf_split(hm.y, uh.y, ul.y);
                tf_split(hm.z, uh.z, ul.z);
                tf_split(hm.w, uh.w, ul.w);
                *(uint4*)(g_hh + (size_t)pb * HH + pj) = uh;
                *(uint4*)(g_hl + (size_t)pb * HH + pj) = ul;
            }
        }

        // barrier B (skip after final step)
        if (t < TT - 1) {
            tgt += 128;
            __syncthreads();
            if (tid == 0) {
                __threadfence();
                atomicAdd(&g_bar, 1u);
                while (*((volatile unsigned*)&g_bar) < tgt) { }
                __threadfence();
            }
            __syncthreads();
        }
    }
}

// ---------------------------------------------------------------------------
// value[m] = sum_j critic[m,j] * W2[j] + b2 ; one block per row m
// ---------------------------------------------------------------------------
__global__ __launch_bounds__(256)
void value_kernel(const float* __restrict__ critic, const float* __restrict__ W2,
                  const float* __restrict__ b2, float* __restrict__ out)
{
    const int m   = blockIdx.x;
    const int tid = threadIdx.x;
    float s = 0.f;
    const float* row = critic + (size_t)m * HH;
    for (int j = tid * 4; j < HH; j += 256 * 4) {
        float4 c4 = *(const float4*)(row + j);
        float4 w4 = *(const float4*)(W2 + j);
        s += c4.x * w4.x + c4.y * w4.y + c4.z * w4.z + c4.w * w4.w;
    }
    #pragma unroll
    for (int off = 16; off > 0; off >>= 1)
        s += __shfl_down_sync(0xffffffffu, s, off);
    __shared__ float red[8];
    if ((tid & 31) == 0) red[tid >> 5] = s;
    __syncthreads();
    if (tid == 0) {
        float t = 0.f;
        #pragma unroll
        for (int w = 0; w < 8; w++) t += red[w];
        out[m] = t + b2[0];
    }
}

__global__ void copy_hout(const float* __restrict__ src, float* __restrict__ dst)
{
    const int i = (blockIdx.x * blockDim.x + threadIdx.x) * 4;
    *(float4*)&dst[i] = *(const float4*)&src[i];
}

// ---------------------------------------------------------------------------
// Launch
// ---------------------------------------------------------------------------
extern "C" void kernel_launch(void* const* d_in, const int* in_sizes, int n_in,
                              void* d_out, int out_size)
{
    const float* hidden = (const float*)d_in[0];
    const float* ws     = (const float*)d_in[1];
    const void*  dones  = (const void*)d_in[2];
    const float* W_emb  = (const float*)d_in[3];
    const float* b_emb  = (const float*)d_in[4];
    const float* Wi     = (const float*)d_in[5];
    const float* bi     = (const float*)d_in[6];
    const float* Wh     = (const float*)d_in[7];
    const float* bhn    = (const float*)d_in[8];
    const float* W1     = (const float*)d_in[9];
    const float* b1     = (const float*)d_in[10];
    const float* W2     = (const float*)d_in[11];
    const float* b2     = (const float*)d_in[12];
    float* out = (float*)d_out;

    float *emb, *xi, *y, *critic, *mask;
    unsigned *whh, *whl, *wembh, *wembl, *wih, *wil, *w1h, *w1l;
    unsigned* barp;
    cudaGetSymbolAddress((void**)&emb,    g_emb);
    cudaGetSymbolAddress((void**)&xi,     g_xi);
    cudaGetSymbolAddress((void**)&y,      g_y);
    cudaGetSymbolAddress((void**)&critic, g_critic);
    cudaGetSymbolAddress((void**)&mask,   g_mask);
    cudaGetSymbolAddress((void**)&whh,    g_whh);
    cudaGetSymbolAddress((void**)&whl,    g_whl);
    cudaGetSymbolAddress((void**)&wembh,  g_wembh);
    cudaGetSymbolAddress((void**)&wembl,  g_wembl);
    cudaGetSymbolAddress((void**)&wih,    g_wih);
    cudaGetSymbolAddress((void**)&wil,    g_wil);
    cudaGetSymbolAddress((void**)&w1h,    g_w1h);
    cudaGetSymbolAddress((void**)&w1l,    g_w1l);
    cudaGetSymbolAddress((void**)&barp,   g_bar);

    // 0) barrier reset; mask; weight/state prep (all constant splits)
    cudaMemsetAsync(barp, 0, sizeof(unsigned));
    detect_mask_mode<<<1, 256>>>((const unsigned int*)dones);
    expand_mask<<<MM / 256, 256>>>(dones, mask);
    split_mat<<<(int)(((size_t)HH * H3) / 256), 256>>>(Wh, whh, whl, HH * H3);
    split_mat<<<(int)(((size_t)OBS * HH) / 256), 256>>>(W_emb, wembh, wembl, OBS * HH);
    split_mat<<<(int)(((size_t)HH * H3) / 256), 256>>>(Wi, wih, wil, HH * H3);
    split_mat<<<(int)(((size_t)HH * HH) / 256), 256>>>(W1, w1h, w1l, HH * HH);
    init_h<<<(BB * HH) / 256, 256>>>(hidden, mask);

    // 1) emb = relu(WS @ W_emb + b_emb)
    {
        dim3 grid(HH / 128, MM / 128);
        mma_gemm<1><<<grid, 256>>>(ws, wembh, wembl, b_emb, emb, MM, HH, OBS);
    }
    // 2) xi = emb @ Wi + bi
    {
        dim3 grid(H3 / 128, MM / 128);
        mma_gemm<0><<<grid, 256>>>(emb, wih, wil, bi, xi, MM, H3, HH);
    }
    // 3) GRU scan: persistent tensor-core kernel
    {
        dim3 grid(COLG, KQ);   // 128 blocks
        gru_scan_mma<<<grid, 256>>>(mask, xi, bhn, y);
    }
    // 4) critic = relu(y @ W1 + b1)
    {
        dim3 grid(HH / 128, MM / 128);
        mma_gemm<1><<<grid, 256>>>(y, w1h, w1l, b1, critic, MM, HH, HH);
    }
    // 5) value -> out[131072 ..)
    value_kernel<<<MM, 256>>>(critic, W2, b2, out + (size_t)BB * HH);
    // 6) h_out = y[T-1] -> out[0 .. 131072)
    copy_hout<<<(BB * HH / 4) / 256, 256>>>(y + (size_t)(TT - 1) * BB * HH, out);
}